// round 5
// baseline (speedup 1.0000x reference)
#include <cuda_runtime.h>
#include <cuda_bf16.h>
#include <cstdint>
#include <math.h>

#define N_NODESC   50000
#define N_EDGESC   800000
#define DIM        512
#define KTOT       1024
#define NUM_GRAPHS 64
#define NUM_CLASSES 10
#define SCAN_NB    ((N_NODESC + 1 + 1023) / 1024)   // 49

typedef unsigned short u16;
typedef unsigned int   u32;

// ---------------- scratch (device globals; no allocation allowed) ----------
__device__ __align__(16) u16  g_xhi [(size_t)N_NODESC * DIM];
__device__ __align__(16) u16  g_xlo [(size_t)N_NODESC * DIM];
__device__ __align__(16) u16  g_aghi[(size_t)N_NODESC * DIM];
__device__ __align__(16) u16  g_aglo[(size_t)N_NODESC * DIM];
__device__ __align__(16) u16  g_h1hi[(size_t)N_NODESC * DIM];
__device__ __align__(16) u16  g_h1lo[(size_t)N_NODESC * DIM];
__device__ __align__(16) float g_h1 [(size_t)N_NODESC * DIM];
__device__ __align__(16) float g_h2 [(size_t)N_NODESC * DIM];
__device__ __align__(16) u16  g_Wb [2][2][(size_t)DIM * KTOT];  // [layer][hi/lo][n][k]
__device__ int   g_rowptr[N_NODESC + 1];
__device__ int   g_fill  [N_NODESC];
__device__ int   g_csr   [N_EDGESC];
__device__ int   g_hcol [2][4 * DIM];
__device__ float g_hsign[2][4 * DIM];
__device__ float g_gsum[NUM_GRAPHS * DIM];
__device__ float g_gcnt[NUM_GRAPHS];
__device__ int   g_bsum[64];
__device__ unsigned g_nz_ei;
__device__ unsigned g_nz_batch;

// ---------------- helpers ---------------------------------------------------
__device__ __forceinline__ float eluf(float x) { return x > 0.f ? x : expm1f(x); }

__device__ __forceinline__ int idx_at(const int* p, long long i, bool is64) {
    return is64 ? p[2 * i] : p[i];
}

// bf16 hi/lo split: v ~= hi + lo, each bf16
__device__ __forceinline__ void bsplit(float v, u16& hi, u16& lo) {
    __nv_bfloat16 h = __float2bfloat16(v);
    hi = __bfloat16_as_ushort(h);
    lo = __bfloat16_as_ushort(__float2bfloat16(v - __bfloat162float(h)));
}

__device__ __forceinline__ void mma_bf16(float* d, const u32* a, const u32* b) {
    asm volatile(
        "mma.sync.aligned.m16n8k16.row.col.f32.bf16.bf16.f32 "
        "{%0,%1,%2,%3},{%4,%5,%6,%7},{%8,%9},{%0,%1,%2,%3};\n"
        : "+f"(d[0]), "+f"(d[1]), "+f"(d[2]), "+f"(d[3])
        : "r"(a[0]), "r"(a[1]), "r"(a[2]), "r"(a[3]), "r"(b[0]), "r"(b[1]));
}
__device__ __forceinline__ void cp16(u32 dst, const void* src) {
    asm volatile("cp.async.cg.shared.global [%0], [%1], 16;\n" :: "r"(dst), "l"(src));
}
__device__ __forceinline__ void cp16z(u32 dst, const void* src, int nbytes) {
    asm volatile("cp.async.cg.shared.global [%0], [%1], 16, %2;\n"
                 :: "r"(dst), "l"(src), "r"(nbytes));
}
__device__ __forceinline__ u32 smem_u32(const void* p) {
    u32 a;
    asm("{ .reg .u64 t; cvta.to.shared.u64 t, %1; cvt.u32.u64 %0, t; }" : "=r"(a) : "l"(p));
    return a;
}

// ---------------- dtype detection ------------------------------------------
__global__ void k_flags_init() {
    if (threadIdx.x == 0) { g_nz_ei = 0u; g_nz_batch = 0u; }
}
__global__ void k_detect(const unsigned* __restrict__ p, long long n, int which) {
    unsigned acc = 0;
    for (long long i = blockIdx.x * blockDim.x + threadIdx.x; i < n;
         i += (long long)gridDim.x * blockDim.x)
        acc |= p[2 * i + 1];
    acc |= __shfl_xor_sync(0xffffffffu, acc, 16);
    acc |= __shfl_xor_sync(0xffffffffu, acc, 8);
    acc |= __shfl_xor_sync(0xffffffffu, acc, 4);
    acc |= __shfl_xor_sync(0xffffffffu, acc, 2);
    acc |= __shfl_xor_sync(0xffffffffu, acc, 1);
    if ((threadIdx.x & 31) == 0 && acc) {
        if (which == 0) atomicOr(&g_nz_ei, acc);
        else            atomicOr(&g_nz_batch, acc);
    }
}

// ---------------- setup kernels --------------------------------------------
__global__ void k_zero_meta() {
    int i = blockIdx.x * blockDim.x + threadIdx.x;
    if (i <= N_NODESC) g_rowptr[i] = 0;
    if (i < NUM_GRAPHS * DIM) g_gsum[i] = 0.f;
    if (i < NUM_GRAPHS) g_gcnt[i] = 0.f;
}

__global__ void k_count(const int* __restrict__ ei) {
    bool is64 = (g_nz_ei == 0u);
    int e = blockIdx.x * blockDim.x + threadIdx.x;
    if (e < N_EDGESC) {
        int s = idx_at(ei, e, is64);
        atomicAdd(&g_rowptr[s + 1], 1);
    }
}

__global__ void k_scan1() {
    __shared__ int wsum[8];
    int b = blockIdx.x, t = threadIdx.x;
    int base = b * 1024 + t * 4;
    int v0, v1, v2, v3;
    v0 = (base + 0 <= N_NODESC) ? g_rowptr[base + 0] : 0;
    v1 = (base + 1 <= N_NODESC) ? g_rowptr[base + 1] : 0;
    v2 = (base + 2 <= N_NODESC) ? g_rowptr[base + 2] : 0;
    v3 = (base + 3 <= N_NODESC) ? g_rowptr[base + 3] : 0;
    v1 += v0; v2 += v1; v3 += v2;
    int lane = t & 31, w = t >> 5;
    int s = v3;
    #pragma unroll
    for (int o = 1; o < 32; o <<= 1) {
        int n = __shfl_up_sync(0xffffffffu, s, o);
        if (lane >= o) s += n;
    }
    if (lane == 31) wsum[w] = s;
    __syncthreads();
    if (t < 8) {
        int x = wsum[t];
        #pragma unroll
        for (int o = 1; o < 8; o <<= 1) {
            int n = __shfl_up_sync(0x000000ffu, x, o);
            if (t >= o) x += n;
        }
        wsum[t] = x;
    }
    __syncthreads();
    int excl = (w ? wsum[w - 1] : 0) + (s - v3);
    v0 += excl; v1 += excl; v2 += excl; v3 += excl;
    if (base + 0 <= N_NODESC) g_rowptr[base + 0] = v0;
    if (base + 1 <= N_NODESC) g_rowptr[base + 1] = v1;
    if (base + 2 <= N_NODESC) g_rowptr[base + 2] = v2;
    if (base + 3 <= N_NODESC) g_rowptr[base + 3] = v3;
    if (t == 0) g_bsum[b] = wsum[7];
}

__global__ void k_scan2() {
    __shared__ int sh[64];
    int t = threadIdx.x;
    sh[t] = (t < SCAN_NB) ? g_bsum[t] : 0;
    __syncthreads();
    for (int o = 1; o < 64; o <<= 1) {
        int a = (t >= o) ? sh[t - o] : 0;
        __syncthreads();
        sh[t] += a;
        __syncthreads();
    }
    g_bsum[t] = sh[t];
}

__global__ void k_scan3() {
    int b = blockIdx.x, t = threadIdx.x;
    int add = b ? g_bsum[b - 1] : 0;
    int base = b * 1024 + t * 4;
    #pragma unroll
    for (int i = 0; i < 4; ++i) {
        int idx = base + i;
        if (idx <= N_NODESC) {
            int r = g_rowptr[idx] + add;
            g_rowptr[idx] = r;
            if (idx < N_NODESC) g_fill[idx] = r;
        }
    }
}

__global__ void k_scatter(const int* __restrict__ ei) {
    bool is64 = (g_nz_ei == 0u);
    int e = blockIdx.x * blockDim.x + threadIdx.x;
    if (e < N_EDGESC) {
        int s = idx_at(ei, e, is64);
        int d = idx_at(ei, (long long)N_EDGESC + e, is64);
        int pos = atomicAdd(&g_fill[s], 1);
        g_csr[pos] = d;
    }
}

__global__ void k_hash(const float* __restrict__ Hm, int l) {
    int i = blockIdx.x * blockDim.x + threadIdx.x;
    if (i >= 4 * DIM) return;
    const float* row = Hm + (size_t)i * 128;
    int col = 0; float sgn = 0.f;
    for (int c = 0; c < 128; ++c) {
        float v = row[c];
        if (v != 0.f) { col = c; sgn = v; }
    }
    g_hcol[l][i] = col;
    g_hsign[l][i] = sgn;
}

// g_Wb[l][hi/lo][n=j][k=r] = bf16 split of cat(Ws, Wp_eff)[r][j]
__global__ void k_buildW(const float* __restrict__ Wp, const float* __restrict__ Ws, int l) {
    int idx = blockIdx.x * blockDim.x + threadIdx.x;
    if (idx >= KTOT * DIM) return;
    int r = idx >> 9;        // k: 0..1023
    int j = idx & 511;       // n: 0..511
    float w;
    if (r < 512) {
        w = Ws[r * DIM + j];
    } else {
        int d = r - 512;
        w = 0.f;
        #pragma unroll
        for (int k = 0; k < 4; ++k) {
            int c = g_hcol[l][k * DIM + d];
            w += g_hsign[l][k * DIM + d] * Wp[(size_t)(k * 128 + c) * DIM + j];
        }
    }
    u16 hi, lo; bsplit(w, hi, lo);
    g_Wb[l][0][(size_t)j * KTOT + r] = hi;
    g_Wb[l][1][(size_t)j * KTOT + r] = lo;
}

// convert x -> bf16 hi/lo planes
__global__ void k_copy_x(const float* __restrict__ x) {
    int i = blockIdx.x * blockDim.x + threadIdx.x;   // float4 index
    if (i >= N_NODESC * (DIM / 4)) return;
    size_t off = (size_t)i * 4;
    float4 v = *(const float4*)(x + off);
    u16 h0, l0, h1, l1, h2, l2, h3, l3;
    bsplit(v.x, h0, l0); bsplit(v.y, h1, l1);
    bsplit(v.z, h2, l2); bsplit(v.w, h3, l3);
    uint2 ph, pl;
    ph.x = (u32)h0 | ((u32)h1 << 16); ph.y = (u32)h2 | ((u32)h3 << 16);
    pl.x = (u32)l0 | ((u32)l1 << 16); pl.y = (u32)l2 | ((u32)l3 << 16);
    *(uint2*)(g_xhi + off) = ph;
    *(uint2*)(g_xlo + off) = pl;
}

// ---------------- aggregation: gather-mean fp32 -> bf16 planes ---------------
__global__ void k_agg(const float* __restrict__ h,
                      u16* __restrict__ ahi, u16* __restrict__ alo) {
    int n = blockIdx.x;
    int t = threadIdx.x;                 // 128 threads, float4 each
    int s = g_rowptr[n], e = g_rowptr[n + 1];
    float4 o;
    if (e == s) {
        o = *(const float4*)(h + (size_t)n * DIM + t * 4);
    } else {
        float4 a = make_float4(0.f, 0.f, 0.f, 0.f);
        for (int j = s; j < e; ++j) {
            int d = g_csr[j];
            float4 v = *(const float4*)(h + (size_t)d * DIM + t * 4);
            a.x += v.x; a.y += v.y; a.z += v.z; a.w += v.w;
        }
        float inv = 1.f / (float)(e - s);
        o = make_float4(a.x * inv, a.y * inv, a.z * inv, a.w * inv);
    }
    u16 h0, l0, h1, l1, h2, l2, h3, l3;
    bsplit(o.x, h0, l0); bsplit(o.y, h1, l1);
    bsplit(o.z, h2, l2); bsplit(o.w, h3, l3);
    uint2 ph, pl;
    ph.x = (u32)h0 | ((u32)h1 << 16); ph.y = (u32)h2 | ((u32)h3 << 16);
    pl.x = (u32)l0 | ((u32)l1 << 16); pl.y = (u32)l2 | ((u32)l3 << 16);
    size_t off = (size_t)n * DIM + t * 4;
    *(uint2*)(ahi + off) = ph;
    *(uint2*)(alo + off) = pl;
}

// ---------------- bf16 split GEMM: out = elu([h|agg] @ (Whi+Wlo) + b) --------
// BM=128, BN=128, BK=32. smem planes (per stage): Ahi, Alo, Bhi, Blo,
// each [128 rows][20 words] (16 data words = 32 bf16 + pad), 16B-aligned chunks.
#define AW       20
#define PLANE    (128 * AW)              // 2560 words
#define STAGEW   (4 * PLANE)             // 10240 words
#define GEMM_SMEM (2 * STAGEW * 4)       // 81920 bytes

__global__ void __launch_bounds__(256, 2)
k_gemmb(const u16* __restrict__ Hhi, const u16* __restrict__ Hlo,
        const u16* __restrict__ Ghi, const u16* __restrict__ Glo,
        const u16* __restrict__ Whi, const u16* __restrict__ Wlo,
        const float* __restrict__ bias, float* __restrict__ C,
        u16* __restrict__ Ohi, u16* __restrict__ Olo, int wplanes)
{
    extern __shared__ u32 S[];
    const u32 sb  = smem_u32(S);
    const int tid  = threadIdx.x;
    const int lane = tid & 31;
    const int wid  = tid >> 5;
    const int g    = lane >> 2;
    const int t4   = lane & 3;
    const int wm   = (wid & 1) * 64;
    const int wn   = (wid >> 1) * 32;
    const int m0   = blockIdx.y * 128;
    const int n0   = blockIdx.x * 128;

    float acc[4][4][4];
    #pragma unroll
    for (int i = 0; i < 4; ++i)
        #pragma unroll
        for (int j = 0; j < 4; ++j)
            #pragma unroll
            for (int k = 0; k < 4; ++k) acc[i][j][k] = 0.f;

    // chunk mapping: 512 chunks per plane (128 rows x 4 x 16B), 2 per thread
    const int r0c = tid >> 2;            // row for chunk set 0 (i=0): q=tid
    const int k0c = tid & 3;
    // i=1: q = tid+256 -> row r0c+64, same kc

    auto load_stage = [&](int kt) {
        const int st = kt & 1;
        const int kk = kt * 32;
        const u16* Ah = (kk & 512) ? Ghi : Hhi;
        const u16* Al = (kk & 512) ? Glo : Hlo;
        const int kc = (kk & 511);
        const u32 abase = sb + (st * STAGEW) * 4;
        #pragma unroll
        for (int i = 0; i < 2; ++i) {
            int row = r0c + i * 64;
            int grow = m0 + row;
            int ok = (grow < N_NODESC) ? 16 : 0;
            size_t so = (size_t)(grow < N_NODESC ? grow : 0) * DIM + kc + k0c * 8;
            u32 d = abase + row * (AW * 4) + k0c * 16;
            cp16z(d, Ah + so, ok);
            cp16z(d + PLANE * 4, Al + so, ok);
        }
        const u32 bbase = sb + (st * STAGEW + 2 * PLANE) * 4;
        #pragma unroll
        for (int i = 0; i < 2; ++i) {
            int row = r0c + i * 64;
            size_t so = (size_t)(n0 + row) * KTOT + kk + k0c * 8;
            u32 d = bbase + row * (AW * 4) + k0c * 16;
            cp16(d, Whi + so);
            cp16(d + PLANE * 4, Wlo + so);
        }
        asm volatile("cp.async.commit_group;\n");
    };

    load_stage(0);
    load_stage(1);

    const int KT = KTOT / 32;   // 32
    for (int kt = 0; kt < KT; ++kt) {
        const int st = kt & 1;
        asm volatile("cp.async.wait_group 1;\n");
        __syncthreads();
        const u32* Ah_ = S + st * STAGEW;
        const u32* Al_ = Ah_ + PLANE;
        const u32* Bh_ = Al_ + PLANE;
        const u32* Bl_ = Bh_ + PLANE;
        #pragma unroll
        for (int ks2 = 0; ks2 < 2; ++ks2) {
            const int w0 = ks2 * 8 + t4;
            const int w1 = w0 + 4;
            u32 ahi[4][4], bhi[4][2];
            #pragma unroll
            for (int mi = 0; mi < 4; ++mi) {
                int r = wm + mi * 16 + g;
                ahi[mi][0] = Ah_[r * AW + w0];
                ahi[mi][1] = Ah_[(r + 8) * AW + w0];
                ahi[mi][2] = Ah_[r * AW + w1];
                ahi[mi][3] = Ah_[(r + 8) * AW + w1];
            }
            #pragma unroll
            for (int ni = 0; ni < 4; ++ni) {
                int r = wn + ni * 8 + g;
                bhi[ni][0] = Bh_[r * AW + w0];
                bhi[ni][1] = Bh_[r * AW + w1];
            }
            #pragma unroll
            for (int mi = 0; mi < 4; ++mi)
                #pragma unroll
                for (int ni = 0; ni < 4; ++ni)
                    mma_bf16(acc[mi][ni], ahi[mi], bhi[ni]);
            // alo x bhi
            {
                u32 alo[4][4];
                #pragma unroll
                for (int mi = 0; mi < 4; ++mi) {
                    int r = wm + mi * 16 + g;
                    alo[mi][0] = Al_[r * AW + w0];
                    alo[mi][1] = Al_[(r + 8) * AW + w0];
                    alo[mi][2] = Al_[r * AW + w1];
                    alo[mi][3] = Al_[(r + 8) * AW + w1];
                }
                #pragma unroll
                for (int mi = 0; mi < 4; ++mi)
                    #pragma unroll
                    for (int ni = 0; ni < 4; ++ni)
                        mma_bf16(acc[mi][ni], alo[mi], bhi[ni]);
            }
            // ahi x blo
            {
                u32 blo[4][2];
                #pragma unroll
                for (int ni = 0; ni < 4; ++ni) {
                    int r = wn + ni * 8 + g;
                    blo[ni][0] = Bl_[r * AW + w0];
                    blo[ni][1] = Bl_[r * AW + w1];
                }
                #pragma unroll
                for (int mi = 0; mi < 4; ++mi)
                    #pragma unroll
                    for (int ni = 0; ni < 4; ++ni)
                        mma_bf16(acc[mi][ni], ahi[mi], blo[ni]);
            }
        }
        __syncthreads();
        if (kt + 2 < KT) load_stage(kt + 2);
    }

    // epilogue: bias + elu (+ optional bf16 plane outputs)
    #pragma unroll
    for (int mi = 0; mi < 4; ++mi) {
        int rr0 = m0 + wm + mi * 16 + g;
        #pragma unroll
        for (int ni = 0; ni < 4; ++ni) {
            int col = n0 + wn + ni * 8 + 2 * t4;
            float bb0 = bias[col], bb1 = bias[col + 1];
            #pragma unroll
            for (int half = 0; half < 2; ++half) {
                int row = rr0 + half * 8;
                if (row < N_NODESC) {
                    float vx = eluf(acc[mi][ni][half * 2 + 0] + bb0);
                    float vy = eluf(acc[mi][ni][half * 2 + 1] + bb1);
                    size_t off = (size_t)row * DIM + col;
                    *(float2*)(C + off) = make_float2(vx, vy);
                    if (wplanes) {
                        u16 hx, lx, hy, ly;
                        bsplit(vx, hx, lx); bsplit(vy, hy, ly);
                        *(u32*)(Ohi + off) = (u32)hx | ((u32)hy << 16);
                        *(u32*)(Olo + off) = (u32)lx | ((u32)ly << 16);
                    }
                }
            }
        }
    }
}

// ---------------- pooling + classifier --------------------------------------
__global__ void k_pool(const float* __restrict__ h, const int* __restrict__ batch) {
    bool is64 = (g_nz_batch == 0u);
    int d  = blockIdx.y * 128 + threadIdx.x;
    int n0 = blockIdx.x * 128;
    int ne = min(n0 + 128, N_NODESC);
    int cur = idx_at(batch, n0, is64);
    float acc = 0.f;
    for (int n = n0; n < ne; ++n) {
        int b = idx_at(batch, n, is64);
        if (b != cur) { atomicAdd(&g_gsum[cur * DIM + d], acc); acc = 0.f; cur = b; }
        acc += h[(size_t)n * DIM + d];
    }
    atomicAdd(&g_gsum[cur * DIM + d], acc);
}

__global__ void k_cnt(const int* __restrict__ batch) {
    bool is64 = (g_nz_batch == 0u);
    int n = blockIdx.x * blockDim.x + threadIdx.x;
    if (n < N_NODESC) atomicAdd(&g_gcnt[idx_at(batch, n, is64)], 1.f);
}

__global__ void k_cls(const float* __restrict__ Wc, const float* __restrict__ bc,
                      float* __restrict__ out) {
    int gid = blockIdx.x;
    int t = threadIdx.x;
    __shared__ float gv[DIM];
    __shared__ float red[NUM_CLASSES][128];
    float inv = 1.f / fmaxf(g_gcnt[gid], 1.f);
    for (int d = t; d < DIM; d += 128) gv[d] = g_gsum[gid * DIM + d] * inv;
    __syncthreads();
    float p[NUM_CLASSES];
    #pragma unroll
    for (int c = 0; c < NUM_CLASSES; ++c) p[c] = 0.f;
    for (int d = t; d < DIM; d += 128) {
        float v = gv[d];
        #pragma unroll
        for (int c = 0; c < NUM_CLASSES; ++c) p[c] += v * Wc[d * NUM_CLASSES + c];
    }
    #pragma unroll
    for (int c = 0; c < NUM_CLASSES; ++c) red[c][t] = p[c];
    __syncthreads();
    for (int off = 64; off > 0; off >>= 1) {
        if (t < off)
            #pragma unroll
            for (int c = 0; c < NUM_CLASSES; ++c) red[c][t] += red[c][t + off];
        __syncthreads();
    }
    if (t < NUM_CLASSES) out[gid * NUM_CLASSES + t] = red[t][0] + bc[t];
}

// ---------------- launch -----------------------------------------------------
extern "C" void kernel_launch(void* const* d_in, const int* in_sizes, int n_in,
                              void* d_out, int out_size) {
    const float* x     = (const float*)d_in[0];
    const int*   ei    = (const int*)d_in[1];
    const int*   batch = (const int*)d_in[2];
    const float* Hm1   = (const float*)d_in[3];
    const float* Wp1   = (const float*)d_in[4];
    const float* Ws1   = (const float*)d_in[5];
    const float* b1    = (const float*)d_in[6];
    const float* Hm2   = (const float*)d_in[7];
    const float* Wp2   = (const float*)d_in[8];
    const float* Ws2   = (const float*)d_in[9];
    const float* b2    = (const float*)d_in[10];
    const float* Wc    = (const float*)d_in[11];
    const float* bc    = (const float*)d_in[12];
    float*       out   = (float*)d_out;

    u16 *xhi, *xlo, *aghi, *aglo, *h1hi, *h1lo, *wb;
    float *h1p, *h2p;
    cudaGetSymbolAddress((void**)&xhi,  g_xhi);
    cudaGetSymbolAddress((void**)&xlo,  g_xlo);
    cudaGetSymbolAddress((void**)&aghi, g_aghi);
    cudaGetSymbolAddress((void**)&aglo, g_aglo);
    cudaGetSymbolAddress((void**)&h1hi, g_h1hi);
    cudaGetSymbolAddress((void**)&h1lo, g_h1lo);
    cudaGetSymbolAddress((void**)&h1p,  g_h1);
    cudaGetSymbolAddress((void**)&h2p,  g_h2);
    cudaGetSymbolAddress((void**)&wb,   g_Wb);
    u16* W0h = wb;
    u16* W0l = wb + (size_t)DIM * KTOT;
    u16* W1h = wb + (size_t)2 * DIM * KTOT;
    u16* W1l = wb + (size_t)3 * DIM * KTOT;

    cudaFuncSetAttribute(k_gemmb, cudaFuncAttributeMaxDynamicSharedMemorySize, GEMM_SMEM);

    // dtype detection
    k_flags_init<<<1, 32>>>();
    k_detect<<<256, 256>>>((const unsigned*)ei, N_EDGESC, 0);
    k_detect<<<64, 256>>>((const unsigned*)batch, N_NODESC / 2, 1);

    // setup
    k_zero_meta<<<196, 256>>>();
    k_count<<<(N_EDGESC + 255) / 256, 256>>>(ei);
    k_scan1<<<SCAN_NB, 256>>>();
    k_scan2<<<1, 64>>>();
    k_scan3<<<SCAN_NB, 256>>>();
    k_scatter<<<(N_EDGESC + 255) / 256, 256>>>(ei);
    k_hash<<<8, 256>>>(Hm1, 0);
    k_hash<<<8, 256>>>(Hm2, 1);
    k_buildW<<<(KTOT * DIM + 255) / 256, 256>>>(Wp1, Ws1, 0);
    k_buildW<<<(KTOT * DIM + 255) / 256, 256>>>(Wp2, Ws2, 1);
    k_copy_x<<<(N_NODESC * (DIM / 4) + 255) / 256, 256>>>(x);

    dim3 ggrid(DIM / 128, (N_NODESC + 127) / 128);   // (4, 391)

    // layer 1
    k_agg<<<N_NODESC, 128>>>(x, aghi, aglo);
    k_gemmb<<<ggrid, 256, GEMM_SMEM>>>(xhi, xlo, aghi, aglo, W0h, W0l,
                                       b1, h1p, h1hi, h1lo, 1);
    // layer 2
    k_agg<<<N_NODESC, 128>>>(h1p, aghi, aglo);
    k_gemmb<<<ggrid, 256, GEMM_SMEM>>>(h1hi, h1lo, aghi, aglo, W1h, W1l,
                                       b2, h2p, (u16*)0, (u16*)0, 0);

    // pool + classify
    k_pool<<<dim3((N_NODESC + 127) / 128, 4), 128>>>(h2p, batch);
    k_cnt<<<196, 256>>>(batch);
    k_cls<<<NUM_GRAPHS, 128>>>(Wc, bc, out);
}

// round 6
// speedup vs baseline: 1.8927x; 1.8927x over previous
#include <cuda_runtime.h>
#include <cuda_fp16.h>
#include <cstdint>
#include <math.h>

#define N_NODESC   50000
#define N_EDGESC   800000
#define DIM        512
#define KTOT       1024
#define NUM_GRAPHS 64
#define NUM_CLASSES 10
#define SCAN_NB    ((N_NODESC + 1 + 1023) / 1024)   // 49

typedef unsigned short u16;
typedef unsigned int   u32;

// ---------------- scratch (device globals; no allocation allowed) ----------
__device__ __align__(16) u16   g_xh [(size_t)N_NODESC * DIM];   // x, fp16
__device__ __align__(16) u16   g_agh[(size_t)N_NODESC * DIM];   // agg, fp16
__device__ __align__(16) u16   g_h1h[(size_t)N_NODESC * DIM];   // h1, fp16
__device__ __align__(16) float g_h2 [(size_t)N_NODESC * DIM];   // h2, fp32
__device__ __align__(16) u16   g_Wh [2][(size_t)DIM * KTOT];    // [layer][n][k], fp16
__device__ int   g_rowptr[N_NODESC + 1];
__device__ int   g_fill  [N_NODESC];
__device__ int   g_csr   [N_EDGESC];
__device__ int   g_hcol [2][4 * DIM];
__device__ float g_hsign[2][4 * DIM];
__device__ float g_gsum[NUM_GRAPHS * DIM];
__device__ float g_gcnt[NUM_GRAPHS];
__device__ int   g_bsum[64];
__device__ unsigned g_nz_ei;
__device__ unsigned g_nz_batch;

// ---------------- helpers ---------------------------------------------------
__device__ __forceinline__ float eluf(float x) { return x > 0.f ? x : expm1f(x); }

__device__ __forceinline__ int idx_at(const int* p, long long i, bool is64) {
    return is64 ? p[2 * i] : p[i];
}

__device__ __forceinline__ void mma_f16(float* d, const u32* a, const u32* b) {
    asm volatile(
        "mma.sync.aligned.m16n8k16.row.col.f32.f16.f16.f32 "
        "{%0,%1,%2,%3},{%4,%5,%6,%7},{%8,%9},{%0,%1,%2,%3};\n"
        : "+f"(d[0]), "+f"(d[1]), "+f"(d[2]), "+f"(d[3])
        : "r"(a[0]), "r"(a[1]), "r"(a[2]), "r"(a[3]), "r"(b[0]), "r"(b[1]));
}
__device__ __forceinline__ void cp16(u32 dst, const void* src) {
    asm volatile("cp.async.cg.shared.global [%0], [%1], 16;\n" :: "r"(dst), "l"(src));
}
__device__ __forceinline__ void cp16z(u32 dst, const void* src, int nbytes) {
    asm volatile("cp.async.cg.shared.global [%0], [%1], 16, %2;\n"
                 :: "r"(dst), "l"(src), "r"(nbytes));
}
__device__ __forceinline__ u32 smem_u32(const void* p) {
    u32 a;
    asm("{ .reg .u64 t; cvta.to.shared.u64 t, %1; cvt.u32.u64 %0, t; }" : "=r"(a) : "l"(p));
    return a;
}
__device__ __forceinline__ u32 pack2h(float a, float b) {
    __half2 h = __floats2half2_rn(a, b);
    return *reinterpret_cast<u32*>(&h);
}

// ---------------- dtype detection ------------------------------------------
__global__ void k_flags_init() {
    if (threadIdx.x == 0) { g_nz_ei = 0u; g_nz_batch = 0u; }
}
__global__ void k_detect(const unsigned* __restrict__ p, long long n, int which) {
    unsigned acc = 0;
    for (long long i = blockIdx.x * blockDim.x + threadIdx.x; i < n;
         i += (long long)gridDim.x * blockDim.x)
        acc |= p[2 * i + 1];
    acc |= __shfl_xor_sync(0xffffffffu, acc, 16);
    acc |= __shfl_xor_sync(0xffffffffu, acc, 8);
    acc |= __shfl_xor_sync(0xffffffffu, acc, 4);
    acc |= __shfl_xor_sync(0xffffffffu, acc, 2);
    acc |= __shfl_xor_sync(0xffffffffu, acc, 1);
    if ((threadIdx.x & 31) == 0 && acc) {
        if (which == 0) atomicOr(&g_nz_ei, acc);
        else            atomicOr(&g_nz_batch, acc);
    }
}

// ---------------- setup kernels --------------------------------------------
__global__ void k_zero_meta() {
    int i = blockIdx.x * blockDim.x + threadIdx.x;
    if (i <= N_NODESC) g_rowptr[i] = 0;
    if (i < NUM_GRAPHS * DIM) g_gsum[i] = 0.f;
    if (i < NUM_GRAPHS) g_gcnt[i] = 0.f;
}

__global__ void k_count(const int* __restrict__ ei) {
    bool is64 = (g_nz_ei == 0u);
    int e = blockIdx.x * blockDim.x + threadIdx.x;
    if (e < N_EDGESC) {
        int s = idx_at(ei, e, is64);
        atomicAdd(&g_rowptr[s + 1], 1);
    }
}

__global__ void k_scan1() {
    __shared__ int wsum[8];
    int b = blockIdx.x, t = threadIdx.x;
    int base = b * 1024 + t * 4;
    int v0, v1, v2, v3;
    v0 = (base + 0 <= N_NODESC) ? g_rowptr[base + 0] : 0;
    v1 = (base + 1 <= N_NODESC) ? g_rowptr[base + 1] : 0;
    v2 = (base + 2 <= N_NODESC) ? g_rowptr[base + 2] : 0;
    v3 = (base + 3 <= N_NODESC) ? g_rowptr[base + 3] : 0;
    v1 += v0; v2 += v1; v3 += v2;
    int lane = t & 31, w = t >> 5;
    int s = v3;
    #pragma unroll
    for (int o = 1; o < 32; o <<= 1) {
        int n = __shfl_up_sync(0xffffffffu, s, o);
        if (lane >= o) s += n;
    }
    if (lane == 31) wsum[w] = s;
    __syncthreads();
    if (t < 8) {
        int x = wsum[t];
        #pragma unroll
        for (int o = 1; o < 8; o <<= 1) {
            int n = __shfl_up_sync(0x000000ffu, x, o);
            if (t >= o) x += n;
        }
        wsum[t] = x;
    }
    __syncthreads();
    int excl = (w ? wsum[w - 1] : 0) + (s - v3);
    v0 += excl; v1 += excl; v2 += excl; v3 += excl;
    if (base + 0 <= N_NODESC) g_rowptr[base + 0] = v0;
    if (base + 1 <= N_NODESC) g_rowptr[base + 1] = v1;
    if (base + 2 <= N_NODESC) g_rowptr[base + 2] = v2;
    if (base + 3 <= N_NODESC) g_rowptr[base + 3] = v3;
    if (t == 0) g_bsum[b] = wsum[7];
}

__global__ void k_scan2() {
    __shared__ int sh[64];
    int t = threadIdx.x;
    sh[t] = (t < SCAN_NB) ? g_bsum[t] : 0;
    __syncthreads();
    for (int o = 1; o < 64; o <<= 1) {
        int a = (t >= o) ? sh[t - o] : 0;
        __syncthreads();
        sh[t] += a;
        __syncthreads();
    }
    g_bsum[t] = sh[t];
}

__global__ void k_scan3() {
    int b = blockIdx.x, t = threadIdx.x;
    int add = b ? g_bsum[b - 1] : 0;
    int base = b * 1024 + t * 4;
    #pragma unroll
    for (int i = 0; i < 4; ++i) {
        int idx = base + i;
        if (idx <= N_NODESC) {
            int r = g_rowptr[idx] + add;
            g_rowptr[idx] = r;
            if (idx < N_NODESC) g_fill[idx] = r;
        }
    }
}

__global__ void k_scatter(const int* __restrict__ ei) {
    bool is64 = (g_nz_ei == 0u);
    int e = blockIdx.x * blockDim.x + threadIdx.x;
    if (e < N_EDGESC) {
        int s = idx_at(ei, e, is64);
        int d = idx_at(ei, (long long)N_EDGESC + e, is64);
        int pos = atomicAdd(&g_fill[s], 1);
        g_csr[pos] = d;
    }
}

__global__ void k_hash(const float* __restrict__ Hm, int l) {
    int i = blockIdx.x * blockDim.x + threadIdx.x;
    if (i >= 4 * DIM) return;
    const float* row = Hm + (size_t)i * 128;
    int col = 0; float sgn = 0.f;
    for (int c = 0; c < 128; ++c) {
        float v = row[c];
        if (v != 0.f) { col = c; sgn = v; }
    }
    g_hcol[l][i] = col;
    g_hsign[l][i] = sgn;
}

// g_Wh[l][n=j][k=r] = fp16( cat(Ws, Wp_eff)[r][j] )
__global__ void k_buildW(const float* __restrict__ Wp, const float* __restrict__ Ws, int l) {
    int idx = blockIdx.x * blockDim.x + threadIdx.x;
    if (idx >= KTOT * DIM) return;
    int r = idx >> 9;        // k
    int j = idx & 511;       // n
    float w;
    if (r < 512) {
        w = Ws[r * DIM + j];
    } else {
        int d = r - 512;
        w = 0.f;
        #pragma unroll
        for (int k = 0; k < 4; ++k) {
            int c = g_hcol[l][k * DIM + d];
            w += g_hsign[l][k * DIM + d] * Wp[(size_t)(k * 128 + c) * DIM + j];
        }
    }
    __half h = __float2half_rn(w);
    g_Wh[l][(size_t)j * KTOT + r] = *reinterpret_cast<u16*>(&h);
}

// x -> fp16 plane
__global__ void k_copy_x(const float* __restrict__ x) {
    int i = blockIdx.x * blockDim.x + threadIdx.x;   // float4 index
    if (i >= N_NODESC * (DIM / 4)) return;
    size_t off = (size_t)i * 4;
    float4 v = *(const float4*)(x + off);
    uint2 p;
    p.x = pack2h(v.x, v.y);
    p.y = pack2h(v.z, v.w);
    *(uint2*)(g_xh + off) = p;
}

// ---------------- aggregation: gather-mean over fp16 plane -------------------
__global__ void k_agg(const u16* __restrict__ h, u16* __restrict__ agg) {
    int n = blockIdx.x;
    int t = threadIdx.x;                 // 128 threads, 4 halves each
    int s = g_rowptr[n], e = g_rowptr[n + 1];
    size_t off = (size_t)n * DIM + t * 4;
    uint2 o;
    if (e == s) {
        o = *(const uint2*)(h + off);    // exact self-copy
    } else {
        float4 a = make_float4(0.f, 0.f, 0.f, 0.f);
        for (int j = s; j < e; ++j) {
            int d = g_csr[j];
            uint2 v = *(const uint2*)(h + (size_t)d * DIM + t * 4);
            float2 f0 = __half22float2(*reinterpret_cast<__half2*>(&v.x));
            float2 f1 = __half22float2(*reinterpret_cast<__half2*>(&v.y));
            a.x += f0.x; a.y += f0.y; a.z += f1.x; a.w += f1.y;
        }
        float inv = 1.f / (float)(e - s);
        o.x = pack2h(a.x * inv, a.y * inv);
        o.y = pack2h(a.z * inv, a.w * inv);
    }
    *(uint2*)(agg + off) = o;
}

// ---------------- fp16 GEMM: out = elu([h|agg] @ W + b) ----------------------
// BM=128, BN=128, BK=32 halves. smem per stage: A plane + B plane,
// each [128 rows][20 words] (16 data words = 32 halves + 4 pad).
#define AW       20
#define PLANEW   (128 * AW)              // 2560 words
#define STAGEW   (2 * PLANEW)            // 5120 words
#define GEMM_SMEM (2 * STAGEW * 4)       // 40960 bytes

__global__ void __launch_bounds__(256, 2)
k_gemmh(const u16* __restrict__ Hh, const u16* __restrict__ Gh,
        const u16* __restrict__ W, const float* __restrict__ bias,
        float* __restrict__ C32, u16* __restrict__ C16, int out16)
{
    extern __shared__ u32 S[];
    const u32 sb   = smem_u32(S);
    const int tid  = threadIdx.x;
    const int lane = tid & 31;
    const int wid  = tid >> 5;
    const int g    = lane >> 2;
    const int t4   = lane & 3;
    const int wm   = (wid & 1) * 64;
    const int wn   = (wid >> 1) * 32;
    const int m0   = blockIdx.y * 128;
    const int n0   = blockIdx.x * 128;

    float acc[4][4][4];
    #pragma unroll
    for (int i = 0; i < 4; ++i)
        #pragma unroll
        for (int j = 0; j < 4; ++j)
            #pragma unroll
            for (int k = 0; k < 4; ++k) acc[i][j][k] = 0.f;

    const int qr = tid >> 2;     // 0..63 (row base for chunk loads)
    const int qc = tid & 3;      // chunk within row (16B each)

    auto load_stage = [&](int kt) {
        const int st = kt & 1;
        const int kk = kt * 32;
        const u16* Asrc = (kk & 512) ? Gh : Hh;
        const int kc = kk & 511;
        const u32 ab = sb + (st * STAGEW) * 4;
        #pragma unroll
        for (int i = 0; i < 2; ++i) {
            int row = qr + i * 64;
            int grow = m0 + row;
            int ok = (grow < N_NODESC) ? 16 : 0;
            const u16* src = Asrc + (size_t)(grow < N_NODESC ? grow : 0) * DIM + kc + qc * 8;
            cp16z(ab + row * (AW * 4) + qc * 16, src, ok);
        }
        const u32 bb = sb + (st * STAGEW + PLANEW) * 4;
        #pragma unroll
        for (int i = 0; i < 2; ++i) {
            int row = qr + i * 64;
            const u16* src = W + (size_t)(n0 + row) * KTOT + kk + qc * 8;
            cp16(bb + row * (AW * 4) + qc * 16, src);
        }
        asm volatile("cp.async.commit_group;\n");
    };

    load_stage(0);
    load_stage(1);

    const int KT = KTOT / 32;   // 32
    for (int kt = 0; kt < KT; ++kt) {
        const int st = kt & 1;
        asm volatile("cp.async.wait_group 1;\n");
        __syncthreads();
        const u32* A_ = S + st * STAGEW;
        const u32* B_ = A_ + PLANEW;
        #pragma unroll
        for (int ks2 = 0; ks2 < 2; ++ks2) {
            const int w0 = ks2 * 8 + t4;
            const int w1 = w0 + 4;
            u32 a[4][4], b[4][2];
            #pragma unroll
            for (int mi = 0; mi < 4; ++mi) {
                int r = wm + mi * 16 + g;
                a[mi][0] = A_[r * AW + w0];
                a[mi][1] = A_[(r + 8) * AW + w0];
                a[mi][2] = A_[r * AW + w1];
                a[mi][3] = A_[(r + 8) * AW + w1];
            }
            #pragma unroll
            for (int ni = 0; ni < 4; ++ni) {
                int r = wn + ni * 8 + g;
                b[ni][0] = B_[r * AW + w0];
                b[ni][1] = B_[r * AW + w1];
            }
            #pragma unroll
            for (int mi = 0; mi < 4; ++mi)
                #pragma unroll
                for (int ni = 0; ni < 4; ++ni)
                    mma_f16(acc[mi][ni], a[mi], b[ni]);
        }
        __syncthreads();
        if (kt + 2 < KT) load_stage(kt + 2);
    }

    // epilogue: bias + elu -> fp16 plane (layer1) or fp32 (layer2)
    #pragma unroll
    for (int mi = 0; mi < 4; ++mi) {
        int rr0 = m0 + wm + mi * 16 + g;
        #pragma unroll
        for (int ni = 0; ni < 4; ++ni) {
            int col = n0 + wn + ni * 8 + 2 * t4;
            float bb0 = bias[col], bb1 = bias[col + 1];
            #pragma unroll
            for (int half = 0; half < 2; ++half) {
                int row = rr0 + half * 8;
                if (row < N_NODESC) {
                    float vx = eluf(acc[mi][ni][half * 2 + 0] + bb0);
                    float vy = eluf(acc[mi][ni][half * 2 + 1] + bb1);
                    size_t off = (size_t)row * DIM + col;
                    if (out16) *(u32*)(C16 + off) = pack2h(vx, vy);
                    else       *(float2*)(C32 + off) = make_float2(vx, vy);
                }
            }
        }
    }
}

// ---------------- pooling + classifier --------------------------------------
__global__ void k_pool(const float* __restrict__ h, const int* __restrict__ batch) {
    bool is64 = (g_nz_batch == 0u);
    int d  = blockIdx.y * 128 + threadIdx.x;
    int n0 = blockIdx.x * 128;
    int ne = min(n0 + 128, N_NODESC);
    int cur = idx_at(batch, n0, is64);
    float acc = 0.f;
    for (int n = n0; n < ne; ++n) {
        int b = idx_at(batch, n, is64);
        if (b != cur) { atomicAdd(&g_gsum[cur * DIM + d], acc); acc = 0.f; cur = b; }
        acc += h[(size_t)n * DIM + d];
    }
    atomicAdd(&g_gsum[cur * DIM + d], acc);
}

__global__ void k_cnt(const int* __restrict__ batch) {
    bool is64 = (g_nz_batch == 0u);
    int n = blockIdx.x * blockDim.x + threadIdx.x;
    if (n < N_NODESC) atomicAdd(&g_gcnt[idx_at(batch, n, is64)], 1.f);
}

__global__ void k_cls(const float* __restrict__ Wc, const float* __restrict__ bc,
                      float* __restrict__ out) {
    int gid = blockIdx.x;
    int t = threadIdx.x;
    __shared__ float gv[DIM];
    __shared__ float red[NUM_CLASSES][128];
    float inv = 1.f / fmaxf(g_gcnt[gid], 1.f);
    for (int d = t; d < DIM; d += 128) gv[d] = g_gsum[gid * DIM + d] * inv;
    __syncthreads();
    float p[NUM_CLASSES];
    #pragma unroll
    for (int c = 0; c < NUM_CLASSES; ++c) p[c] = 0.f;
    for (int d = t; d < DIM; d += 128) {
        float v = gv[d];
        #pragma unroll
        for (int c = 0; c < NUM_CLASSES; ++c) p[c] += v * Wc[d * NUM_CLASSES + c];
    }
    #pragma unroll
    for (int c = 0; c < NUM_CLASSES; ++c) red[c][t] = p[c];
    __syncthreads();
    for (int off = 64; off > 0; off >>= 1) {
        if (t < off)
            #pragma unroll
            for (int c = 0; c < NUM_CLASSES; ++c) red[c][t] += red[c][t + off];
        __syncthreads();
    }
    if (t < NUM_CLASSES) out[gid * NUM_CLASSES + t] = red[t][0] + bc[t];
}

// ---------------- launch -----------------------------------------------------
extern "C" void kernel_launch(void* const* d_in, const int* in_sizes, int n_in,
                              void* d_out, int out_size) {
    const float* x     = (const float*)d_in[0];
    const int*   ei    = (const int*)d_in[1];
    const int*   batch = (const int*)d_in[2];
    const float* Hm1   = (const float*)d_in[3];
    const float* Wp1   = (const float*)d_in[4];
    const float* Ws1   = (const float*)d_in[5];
    const float* b1    = (const float*)d_in[6];
    const float* Hm2   = (const float*)d_in[7];
    const float* Wp2   = (const float*)d_in[8];
    const float* Ws2   = (const float*)d_in[9];
    const float* b2    = (const float*)d_in[10];
    const float* Wc    = (const float*)d_in[11];
    const float* bc    = (const float*)d_in[12];
    float*       out   = (float*)d_out;

    u16 *xh, *agh, *h1h, *wh;
    float *h2p;
    cudaGetSymbolAddress((void**)&xh,  g_xh);
    cudaGetSymbolAddress((void**)&agh, g_agh);
    cudaGetSymbolAddress((void**)&h1h, g_h1h);
    cudaGetSymbolAddress((void**)&h2p, g_h2);
    cudaGetSymbolAddress((void**)&wh,  g_Wh);
    u16* W0 = wh;
    u16* W1 = wh + (size_t)DIM * KTOT;

    cudaFuncSetAttribute(k_gemmh, cudaFuncAttributeMaxDynamicSharedMemorySize, GEMM_SMEM);

    // dtype detection
    k_flags_init<<<1, 32>>>();
    k_detect<<<256, 256>>>((const unsigned*)ei, N_EDGESC, 0);
    k_detect<<<64, 256>>>((const unsigned*)batch, N_NODESC / 2, 1);

    // setup
    k_zero_meta<<<196, 256>>>();
    k_count<<<(N_EDGESC + 255) / 256, 256>>>(ei);
    k_scan1<<<SCAN_NB, 256>>>();
    k_scan2<<<1, 64>>>();
    k_scan3<<<SCAN_NB, 256>>>();
    k_scatter<<<(N_EDGESC + 255) / 256, 256>>>(ei);
    k_hash<<<8, 256>>>(Hm1, 0);
    k_hash<<<8, 256>>>(Hm2, 1);
    k_buildW<<<(KTOT * DIM + 255) / 256, 256>>>(Wp1, Ws1, 0);
    k_buildW<<<(KTOT * DIM + 255) / 256, 256>>>(Wp2, Ws2, 1);
    k_copy_x<<<(N_NODESC * (DIM / 4) + 255) / 256, 256>>>(x);

    dim3 ggrid(DIM / 128, (N_NODESC + 127) / 128);   // (4, 391)

    // layer 1: agg over x plane; gemm -> h1 fp16 plane
    k_agg<<<N_NODESC, 128>>>(xh, agh);
    k_gemmh<<<ggrid, 256, GEMM_SMEM>>>(xh, agh, W0, b1, (float*)0, h1h, 1);

    // layer 2: agg over h1 plane; gemm -> h2 fp32
    k_agg<<<N_NODESC, 128>>>(h1h, agh);
    k_gemmh<<<ggrid, 256, GEMM_SMEM>>>(h1h, agh, W1, b2, h2p, (u16*)0, 0);

    // pool + classify
    k_pool<<<dim3((N_NODESC + 127) / 128, 4), 128>>>(h2p, batch);
    k_cnt<<<196, 256>>>(batch);
    k_cls<<<NUM_GRAPHS, 128>>>(Wc, bc, out);
}

// round 7
// speedup vs baseline: 1.9769x; 1.0445x over previous
#include <cuda_runtime.h>
#include <cuda_fp16.h>
#include <cstdint>
#include <math.h>

#define N_NODESC   50000
#define N_EDGESC   800000
#define DIM        512
#define KTOT       1024
#define NUM_GRAPHS 64
#define NUM_CLASSES 10
#define SCAN_NB    ((N_NODESC + 1 + 1023) / 1024)   // 49

typedef unsigned short u16;
typedef unsigned int   u32;

// ---------------- scratch (device globals; no allocation allowed) ----------
__device__ __align__(16) u16   g_xh [(size_t)N_NODESC * DIM];   // x, fp16
__device__ __align__(16) u16   g_agh[(size_t)N_NODESC * DIM];   // agg, fp16
__device__ __align__(16) u16   g_h1h[(size_t)N_NODESC * DIM];   // h1, fp16
__device__ __align__(16) u16   g_h2h[(size_t)N_NODESC * DIM];   // h2, fp16
__device__ __align__(16) u16   g_Wh [2][(size_t)DIM * KTOT];    // [layer][n][k], fp16
__device__ int   g_rowptr[N_NODESC + 1];
__device__ int   g_fill  [N_NODESC];
__device__ int   g_csr   [N_EDGESC];
__device__ int   g_hcol [2][4 * DIM];
__device__ float g_hsign[2][4 * DIM];
__device__ float g_gsum[NUM_GRAPHS * DIM];
__device__ float g_gcnt[NUM_GRAPHS];
__device__ int   g_bsum[64];
__device__ unsigned g_nz_ei;
__device__ unsigned g_nz_batch;

// ---------------- helpers ---------------------------------------------------
__device__ __forceinline__ float eluf(float x) { return x > 0.f ? x : expm1f(x); }

__device__ __forceinline__ int idx_at(const int* p, long long i, bool is64) {
    return is64 ? p[2 * i] : p[i];
}

__device__ __forceinline__ void mma_f16(float* d, const u32* a, const u32* b) {
    asm volatile(
        "mma.sync.aligned.m16n8k16.row.col.f32.f16.f16.f32 "
        "{%0,%1,%2,%3},{%4,%5,%6,%7},{%8,%9},{%0,%1,%2,%3};\n"
        : "+f"(d[0]), "+f"(d[1]), "+f"(d[2]), "+f"(d[3])
        : "r"(a[0]), "r"(a[1]), "r"(a[2]), "r"(a[3]), "r"(b[0]), "r"(b[1]));
}
__device__ __forceinline__ void ldm_x4(u32& r0, u32& r1, u32& r2, u32& r3, u32 addr) {
    asm volatile("ldmatrix.sync.aligned.m8n8.x4.shared.b16 {%0,%1,%2,%3}, [%4];"
                 : "=r"(r0), "=r"(r1), "=r"(r2), "=r"(r3) : "r"(addr));
}
__device__ __forceinline__ void cp16(u32 dst, const void* src) {
    asm volatile("cp.async.cg.shared.global [%0], [%1], 16;\n" :: "r"(dst), "l"(src));
}
__device__ __forceinline__ void cp16z(u32 dst, const void* src, int nbytes) {
    asm volatile("cp.async.cg.shared.global [%0], [%1], 16, %2;\n"
                 :: "r"(dst), "l"(src), "r"(nbytes));
}
__device__ __forceinline__ u32 smem_u32(const void* p) {
    u32 a;
    asm("{ .reg .u64 t; cvta.to.shared.u64 t, %1; cvt.u32.u64 %0, t; }" : "=r"(a) : "l"(p));
    return a;
}
__device__ __forceinline__ u32 pack2h(float a, float b) {
    __half2 h = __floats2half2_rn(a, b);
    return *reinterpret_cast<u32*>(&h);
}

// ---------------- dtype detection ------------------------------------------
__global__ void k_flags_init() {
    if (threadIdx.x == 0) { g_nz_ei = 0u; g_nz_batch = 0u; }
}
__global__ void k_detect(const unsigned* __restrict__ p, long long n, int which) {
    unsigned acc = 0;
    for (long long i = blockIdx.x * blockDim.x + threadIdx.x; i < n;
         i += (long long)gridDim.x * blockDim.x)
        acc |= p[2 * i + 1];
    acc |= __shfl_xor_sync(0xffffffffu, acc, 16);
    acc |= __shfl_xor_sync(0xffffffffu, acc, 8);
    acc |= __shfl_xor_sync(0xffffffffu, acc, 4);
    acc |= __shfl_xor_sync(0xffffffffu, acc, 2);
    acc |= __shfl_xor_sync(0xffffffffu, acc, 1);
    if ((threadIdx.x & 31) == 0 && acc) {
        if (which == 0) atomicOr(&g_nz_ei, acc);
        else            atomicOr(&g_nz_batch, acc);
    }
}

// ---------------- setup kernels --------------------------------------------
__global__ void k_zero_meta() {
    int i = blockIdx.x * blockDim.x + threadIdx.x;
    if (i <= N_NODESC) g_rowptr[i] = 0;
    if (i < NUM_GRAPHS * DIM) g_gsum[i] = 0.f;
    if (i < NUM_GRAPHS) g_gcnt[i] = 0.f;
}

__global__ void k_count(const int* __restrict__ ei) {
    bool is64 = (g_nz_ei == 0u);
    int e = blockIdx.x * blockDim.x + threadIdx.x;
    if (e < N_EDGESC) {
        int s = idx_at(ei, e, is64);
        atomicAdd(&g_rowptr[s + 1], 1);
    }
}

__global__ void k_scan1() {
    __shared__ int wsum[8];
    int b = blockIdx.x, t = threadIdx.x;
    int base = b * 1024 + t * 4;
    int v0, v1, v2, v3;
    v0 = (base + 0 <= N_NODESC) ? g_rowptr[base + 0] : 0;
    v1 = (base + 1 <= N_NODESC) ? g_rowptr[base + 1] : 0;
    v2 = (base + 2 <= N_NODESC) ? g_rowptr[base + 2] : 0;
    v3 = (base + 3 <= N_NODESC) ? g_rowptr[base + 3] : 0;
    v1 += v0; v2 += v1; v3 += v2;
    int lane = t & 31, w = t >> 5;
    int s = v3;
    #pragma unroll
    for (int o = 1; o < 32; o <<= 1) {
        int n = __shfl_up_sync(0xffffffffu, s, o);
        if (lane >= o) s += n;
    }
    if (lane == 31) wsum[w] = s;
    __syncthreads();
    if (t < 8) {
        int x = wsum[t];
        #pragma unroll
        for (int o = 1; o < 8; o <<= 1) {
            int n = __shfl_up_sync(0x000000ffu, x, o);
            if (t >= o) x += n;
        }
        wsum[t] = x;
    }
    __syncthreads();
    int excl = (w ? wsum[w - 1] : 0) + (s - v3);
    v0 += excl; v1 += excl; v2 += excl; v3 += excl;
    if (base + 0 <= N_NODESC) g_rowptr[base + 0] = v0;
    if (base + 1 <= N_NODESC) g_rowptr[base + 1] = v1;
    if (base + 2 <= N_NODESC) g_rowptr[base + 2] = v2;
    if (base + 3 <= N_NODESC) g_rowptr[base + 3] = v3;
    if (t == 0) g_bsum[b] = wsum[7];
}

__global__ void k_scan2() {
    __shared__ int sh[64];
    int t = threadIdx.x;
    sh[t] = (t < SCAN_NB) ? g_bsum[t] : 0;
    __syncthreads();
    for (int o = 1; o < 64; o <<= 1) {
        int a = (t >= o) ? sh[t - o] : 0;
        __syncthreads();
        sh[t] += a;
        __syncthreads();
    }
    g_bsum[t] = sh[t];
}

__global__ void k_scan3() {
    int b = blockIdx.x, t = threadIdx.x;
    int add = b ? g_bsum[b - 1] : 0;
    int base = b * 1024 + t * 4;
    #pragma unroll
    for (int i = 0; i < 4; ++i) {
        int idx = base + i;
        if (idx <= N_NODESC) {
            int r = g_rowptr[idx] + add;
            g_rowptr[idx] = r;
            if (idx < N_NODESC) g_fill[idx] = r;
        }
    }
}

__global__ void k_scatter(const int* __restrict__ ei) {
    bool is64 = (g_nz_ei == 0u);
    int e = blockIdx.x * blockDim.x + threadIdx.x;
    if (e < N_EDGESC) {
        int s = idx_at(ei, e, is64);
        int d = idx_at(ei, (long long)N_EDGESC + e, is64);
        int pos = atomicAdd(&g_fill[s], 1);
        g_csr[pos] = d;
    }
}

__global__ void k_hash(const float* __restrict__ Hm, int l) {
    int i = blockIdx.x * blockDim.x + threadIdx.x;
    if (i >= 4 * DIM) return;
    const float* row = Hm + (size_t)i * 128;
    int col = 0; float sgn = 0.f;
    for (int c = 0; c < 128; ++c) {
        float v = row[c];
        if (v != 0.f) { col = c; sgn = v; }
    }
    g_hcol[l][i] = col;
    g_hsign[l][i] = sgn;
}

// g_Wh[l][n=j][k=r] = fp16( cat(Ws, Wp_eff)[r][j] )
__global__ void k_buildW(const float* __restrict__ Wp, const float* __restrict__ Ws, int l) {
    int idx = blockIdx.x * blockDim.x + threadIdx.x;
    if (idx >= KTOT * DIM) return;
    int r = idx >> 9;        // k
    int j = idx & 511;       // n
    float w;
    if (r < 512) {
        w = Ws[r * DIM + j];
    } else {
        int d = r - 512;
        w = 0.f;
        #pragma unroll
        for (int k = 0; k < 4; ++k) {
            int c = g_hcol[l][k * DIM + d];
            w += g_hsign[l][k * DIM + d] * Wp[(size_t)(k * 128 + c) * DIM + j];
        }
    }
    __half h = __float2half_rn(w);
    g_Wh[l][(size_t)j * KTOT + r] = *reinterpret_cast<u16*>(&h);
}

// x -> fp16 plane
__global__ void k_copy_x(const float* __restrict__ x) {
    int i = blockIdx.x * blockDim.x + threadIdx.x;   // float4 index
    if (i >= N_NODESC * (DIM / 4)) return;
    size_t off = (size_t)i * 4;
    float4 v = *(const float4*)(x + off);
    uint2 p;
    p.x = pack2h(v.x, v.y);
    p.y = pack2h(v.z, v.w);
    *(uint2*)(g_xh + off) = p;
}

// ---------------- aggregation: gather-mean over fp16 plane -------------------
__global__ void k_agg(const u16* __restrict__ h, u16* __restrict__ agg) {
    int n = blockIdx.x;
    int t = threadIdx.x;                 // 128 threads, 4 halves each
    int s = g_rowptr[n], e = g_rowptr[n + 1];
    size_t off = (size_t)n * DIM + t * 4;
    uint2 o;
    if (e == s) {
        o = *(const uint2*)(h + off);    // exact self-copy
    } else {
        float4 a = make_float4(0.f, 0.f, 0.f, 0.f);
        for (int j = s; j < e; ++j) {
            int d = g_csr[j];
            uint2 v = *(const uint2*)(h + (size_t)d * DIM + t * 4);
            float2 f0 = __half22float2(*reinterpret_cast<__half2*>(&v.x));
            float2 f1 = __half22float2(*reinterpret_cast<__half2*>(&v.y));
            a.x += f0.x; a.y += f0.y; a.z += f1.x; a.w += f1.y;
        }
        float inv = 1.f / (float)(e - s);
        o.x = pack2h(a.x * inv, a.y * inv);
        o.y = pack2h(a.z * inv, a.w * inv);
    }
    *(uint2*)(agg + off) = o;
}

// ---------------- fp16 GEMM: out = elu([h|agg] @ W + b) ----------------------
// BM=128, BN=128, BK=32 halves. smem per stage: A plane + B plane,
// each [128 rows][80 bytes] (64B data + 16B pad); ldmatrix fragment loads.
#define AWB      80                      // bytes per smem row
#define PLANEB   (128 * AWB)             // 10240 bytes
#define STAGEB   (2 * PLANEB)            // 20480 bytes
#define GEMM_SMEM (2 * STAGEB)           // 40960 bytes

__global__ void __launch_bounds__(256, 2)
k_gemmh(const u16* __restrict__ Hh, const u16* __restrict__ Gh,
        const u16* __restrict__ W, const float* __restrict__ bias,
        u16* __restrict__ C16)
{
    extern __shared__ char S[];
    const u32 sb   = smem_u32(S);
    const int tid  = threadIdx.x;
    const int lane = tid & 31;
    const int wid  = tid >> 5;
    const int g    = lane >> 2;
    const int t4   = lane & 3;
    const int wm   = (wid & 1) * 64;
    const int wn   = (wid >> 1) * 32;
    const int m0   = blockIdx.y * 128;
    const int n0   = blockIdx.x * 128;

    float acc[4][4][4];
    #pragma unroll
    for (int i = 0; i < 4; ++i)
        #pragma unroll
        for (int j = 0; j < 4; ++j)
            #pragma unroll
            for (int k = 0; k < 4; ++k) acc[i][j][k] = 0.f;

    const int qr = tid >> 2;     // 0..63 (row base for chunk loads)
    const int qc = tid & 3;      // 16B chunk within row

    auto load_stage = [&](int kt) {
        const int st = kt & 1;
        const int kk = kt * 32;
        const u16* Asrc = (kk & 512) ? Gh : Hh;
        const int kc = kk & 511;
        const u32 ab = sb + st * STAGEB;
        #pragma unroll
        for (int i = 0; i < 2; ++i) {
            int row = qr + i * 64;
            int grow = m0 + row;
            int ok = (grow < N_NODESC) ? 16 : 0;
            const u16* src = Asrc + (size_t)(grow < N_NODESC ? grow : 0) * DIM + kc + qc * 8;
            cp16z(ab + row * AWB + qc * 16, src, ok);
        }
        const u32 bb = sb + st * STAGEB + PLANEB;
        #pragma unroll
        for (int i = 0; i < 2; ++i) {
            int row = qr + i * 64;
            const u16* src = W + (size_t)(n0 + row) * KTOT + kk + qc * 8;
            cp16(bb + row * AWB + qc * 16, src);
        }
        asm volatile("cp.async.commit_group;\n");
    };

    load_stage(0);
    load_stage(1);

    // ldmatrix address components (constant across slabs except stage base)
    const u32 a_row  = wm + (lane & 15);           // + mi*16
    const u32 a_koff = (lane >> 4) << 4;           // bytes: 0 or 16
    const u32 b_row  = wn + ((lane >> 4) << 3) + (lane & 7);   // + nip*16
    const u32 b_koff = ((lane >> 3) & 1) << 4;

    const int KT = KTOT / 32;   // 32
    for (int kt = 0; kt < KT; ++kt) {
        const int st = kt & 1;
        asm volatile("cp.async.wait_group 1;\n");
        __syncthreads();
        const u32 ab = sb + st * STAGEB;
        const u32 bb = ab + PLANEB;
        #pragma unroll
        for (int ks2 = 0; ks2 < 2; ++ks2) {
            const u32 ko = ks2 << 5;               // 0 or 32 bytes
            u32 a[4][4], b[4][2];
            #pragma unroll
            for (int mi = 0; mi < 4; ++mi)
                ldm_x4(a[mi][0], a[mi][1], a[mi][2], a[mi][3],
                       ab + (a_row + mi * 16) * AWB + a_koff + ko);
            #pragma unroll
            for (int nip = 0; nip < 2; ++nip)
                ldm_x4(b[nip * 2][0], b[nip * 2][1], b[nip * 2 + 1][0], b[nip * 2 + 1][1],
                       bb + (b_row + nip * 16) * AWB + b_koff + ko);
            #pragma unroll
            for (int mi = 0; mi < 4; ++mi)
                #pragma unroll
                for (int ni = 0; ni < 4; ++ni)
                    mma_f16(acc[mi][ni], a[mi], b[ni]);
        }
        __syncthreads();
        if (kt + 2 < KT) load_stage(kt + 2);
    }

    // epilogue: bias + elu -> fp16 plane
    #pragma unroll
    for (int mi = 0; mi < 4; ++mi) {
        int rr0 = m0 + wm + mi * 16 + g;
        #pragma unroll
        for (int ni = 0; ni < 4; ++ni) {
            int col = n0 + wn + ni * 8 + 2 * t4;
            float bb0 = bias[col], bb1 = bias[col + 1];
            #pragma unroll
            for (int half = 0; half < 2; ++half) {
                int row = rr0 + half * 8;
                if (row < N_NODESC) {
                    float vx = eluf(acc[mi][ni][half * 2 + 0] + bb0);
                    float vy = eluf(acc[mi][ni][half * 2 + 1] + bb1);
                    *(u32*)(C16 + (size_t)row * DIM + col) = pack2h(vx, vy);
                }
            }
        }
    }
}

// ---------------- pooling + classifier --------------------------------------
__global__ void k_pool(const u16* __restrict__ h, const int* __restrict__ batch) {
    bool is64 = (g_nz_batch == 0u);
    int d  = blockIdx.y * 128 + threadIdx.x;
    int n0 = blockIdx.x * 128;
    int ne = min(n0 + 128, N_NODESC);
    int cur = idx_at(batch, n0, is64);
    float acc = 0.f;
    for (int n = n0; n < ne; ++n) {
        int b = idx_at(batch, n, is64);
        if (b != cur) { atomicAdd(&g_gsum[cur * DIM + d], acc); acc = 0.f; cur = b; }
        acc += __half2float(*reinterpret_cast<const __half*>(h + (size_t)n * DIM + d));
    }
    atomicAdd(&g_gsum[cur * DIM + d], acc);
}

__global__ void k_cnt(const int* __restrict__ batch) {
    bool is64 = (g_nz_batch == 0u);
    int n = blockIdx.x * blockDim.x + threadIdx.x;
    if (n < N_NODESC) atomicAdd(&g_gcnt[idx_at(batch, n, is64)], 1.f);
}

__global__ void k_cls(const float* __restrict__ Wc, const float* __restrict__ bc,
                      float* __restrict__ out) {
    int gid = blockIdx.x;
    int t = threadIdx.x;
    __shared__ float gv[DIM];
    __shared__ float red[NUM_CLASSES][128];
    float inv = 1.f / fmaxf(g_gcnt[gid], 1.f);
    for (int d = t; d < DIM; d += 128) gv[d] = g_gsum[gid * DIM + d] * inv;
    __syncthreads();
    float p[NUM_CLASSES];
    #pragma unroll
    for (int c = 0; c < NUM_CLASSES; ++c) p[c] = 0.f;
    for (int d = t; d < DIM; d += 128) {
        float v = gv[d];
        #pragma unroll
        for (int c = 0; c < NUM_CLASSES; ++c) p[c] += v * Wc[d * NUM_CLASSES + c];
    }
    #pragma unroll
    for (int c = 0; c < NUM_CLASSES; ++c) red[c][t] = p[c];
    __syncthreads();
    for (int off = 64; off > 0; off >>= 1) {
        if (t < off)
            #pragma unroll
            for (int c = 0; c < NUM_CLASSES; ++c) red[c][t] += red[c][t + off];
        __syncthreads();
    }
    if (t < NUM_CLASSES) out[gid * NUM_CLASSES + t] = red[t][0] + bc[t];
}

// ---------------- launch -----------------------------------------------------
extern "C" void kernel_launch(void* const* d_in, const int* in_sizes, int n_in,
                              void* d_out, int out_size) {
    const float* x     = (const float*)d_in[0];
    const int*   ei    = (const int*)d_in[1];
    const int*   batch = (const int*)d_in[2];
    const float* Hm1   = (const float*)d_in[3];
    const float* Wp1   = (const float*)d_in[4];
    const float* Ws1   = (const float*)d_in[5];
    const float* b1    = (const float*)d_in[6];
    const float* Hm2   = (const float*)d_in[7];
    const float* Wp2   = (const float*)d_in[8];
    const float* Ws2   = (const float*)d_in[9];
    const float* b2    = (const float*)d_in[10];
    const float* Wc    = (const float*)d_in[11];
    const float* bc    = (const float*)d_in[12];
    float*       out   = (float*)d_out;

    u16 *xh, *agh, *h1h, *h2h, *wh;
    cudaGetSymbolAddress((void**)&xh,  g_xh);
    cudaGetSymbolAddress((void**)&agh, g_agh);
    cudaGetSymbolAddress((void**)&h1h, g_h1h);
    cudaGetSymbolAddress((void**)&h2h, g_h2h);
    cudaGetSymbolAddress((void**)&wh,  g_Wh);
    u16* W0 = wh;
    u16* W1 = wh + (size_t)DIM * KTOT;

    cudaFuncSetAttribute(k_gemmh, cudaFuncAttributeMaxDynamicSharedMemorySize, GEMM_SMEM);

    // dtype detection
    k_flags_init<<<1, 32>>>();
    k_detect<<<256, 256>>>((const unsigned*)ei, N_EDGESC, 0);
    k_detect<<<64, 256>>>((const unsigned*)batch, N_NODESC / 2, 1);

    // setup
    k_zero_meta<<<196, 256>>>();
    k_count<<<(N_EDGESC + 255) / 256, 256>>>(ei);
    k_scan1<<<SCAN_NB, 256>>>();
    k_scan2<<<1, 64>>>();
    k_scan3<<<SCAN_NB, 256>>>();
    k_scatter<<<(N_EDGESC + 255) / 256, 256>>>(ei);
    k_hash<<<8, 256>>>(Hm1, 0);
    k_hash<<<8, 256>>>(Hm2, 1);
    k_buildW<<<(KTOT * DIM + 255) / 256, 256>>>(Wp1, Ws1, 0);
    k_buildW<<<(KTOT * DIM + 255) / 256, 256>>>(Wp2, Ws2, 1);
    k_copy_x<<<(N_NODESC * (DIM / 4) + 255) / 256, 256>>>(x);

    dim3 ggrid(DIM / 128, (N_NODESC + 127) / 128);   // (4, 391)

    // layer 1
    k_agg<<<N_NODESC, 128>>>(xh, agh);
    k_gemmh<<<ggrid, 256, GEMM_SMEM>>>(xh, agh, W0, b1, h1h);

    // layer 2
    k_agg<<<N_NODESC, 128>>>(h1h, agh);
    k_gemmh<<<ggrid, 256, GEMM_SMEM>>>(h1h, agh, W1, b2, h2h);

    // pool + classify
    k_pool<<<dim3((N_NODESC + 127) / 128, 4), 128>>>(h2h, batch);
    k_cnt<<<196, 256>>>(batch);
    k_cls<<<NUM_GRAPHS, 128>>>(Wc, bc, out);
}

// round 8
// speedup vs baseline: 2.0222x; 1.0229x over previous
#include <cuda_runtime.h>
#include <cuda_fp16.h>
#include <cstdint>
#include <math.h>

#define N_NODESC   50000
#define N_EDGESC   800000
#define DIM        512
#define KTOT       1024
#define NUM_GRAPHS 64
#define NUM_CLASSES 10
#define SCAN_NB    ((N_NODESC + 1 + 1023) / 1024)   // 49

typedef unsigned short u16;
typedef unsigned int   u32;

// ---------------- scratch (device globals; no allocation allowed) ----------
__device__ __align__(16) u16   g_xh [(size_t)N_NODESC * DIM];   // x, fp16
__device__ __align__(16) u16   g_agh[(size_t)N_NODESC * DIM];   // agg, fp16
__device__ __align__(16) u16   g_h1h[(size_t)N_NODESC * DIM];   // h1, fp16
__device__ __align__(16) u16   g_h2h[(size_t)N_NODESC * DIM];   // h2, fp16
__device__ __align__(16) u16   g_Wh [2][(size_t)DIM * KTOT];    // [layer][n][k], fp16
__device__ int   g_rowptr[N_NODESC + 1];
__device__ int   g_fill  [N_NODESC];
__device__ int   g_csr   [N_EDGESC];
__device__ int   g_hcol [2][4 * DIM];
__device__ float g_hsign[2][4 * DIM];
__device__ float g_gsum[NUM_GRAPHS * DIM];
__device__ float g_gcnt[NUM_GRAPHS];
__device__ int   g_bsum[64];
__device__ unsigned g_nz_ei;
__device__ unsigned g_nz_batch;

// ---------------- helpers ---------------------------------------------------
__device__ __forceinline__ float eluf(float x) { return x > 0.f ? x : expm1f(x); }

__device__ __forceinline__ int idx_at(const int* p, long long i, bool is64) {
    return is64 ? p[2 * i] : p[i];
}

__device__ __forceinline__ void mma_f16(float* d, const u32* a, const u32* b) {
    asm volatile(
        "mma.sync.aligned.m16n8k16.row.col.f32.f16.f16.f32 "
        "{%0,%1,%2,%3},{%4,%5,%6,%7},{%8,%9},{%0,%1,%2,%3};\n"
        : "+f"(d[0]), "+f"(d[1]), "+f"(d[2]), "+f"(d[3])
        : "r"(a[0]), "r"(a[1]), "r"(a[2]), "r"(a[3]), "r"(b[0]), "r"(b[1]));
}
__device__ __forceinline__ void ldm_x4(u32& r0, u32& r1, u32& r2, u32& r3, u32 addr) {
    asm volatile("ldmatrix.sync.aligned.m8n8.x4.shared.b16 {%0,%1,%2,%3}, [%4];"
                 : "=r"(r0), "=r"(r1), "=r"(r2), "=r"(r3) : "r"(addr));
}
__device__ __forceinline__ void cp16(u32 dst, const void* src) {
    asm volatile("cp.async.cg.shared.global [%0], [%1], 16;\n" :: "r"(dst), "l"(src));
}
__device__ __forceinline__ void cp16z(u32 dst, const void* src, int nbytes) {
    asm volatile("cp.async.cg.shared.global [%0], [%1], 16, %2;\n"
                 :: "r"(dst), "l"(src), "r"(nbytes));
}
__device__ __forceinline__ u32 smem_u32(const void* p) {
    u32 a;
    asm("{ .reg .u64 t; cvta.to.shared.u64 t, %1; cvt.u32.u64 %0, t; }" : "=r"(a) : "l"(p));
    return a;
}
__device__ __forceinline__ u32 pack2h(float a, float b) {
    __half2 h = __floats2half2_rn(a, b);
    return *reinterpret_cast<u32*>(&h);
}
__device__ __forceinline__ void acc8(float* a, uint4 v) {
    float2 f0 = __half22float2(*reinterpret_cast<__half2*>(&v.x));
    float2 f1 = __half22float2(*reinterpret_cast<__half2*>(&v.y));
    float2 f2 = __half22float2(*reinterpret_cast<__half2*>(&v.z));
    float2 f3 = __half22float2(*reinterpret_cast<__half2*>(&v.w));
    a[0] += f0.x; a[1] += f0.y; a[2] += f1.x; a[3] += f1.y;
    a[4] += f2.x; a[5] += f2.y; a[6] += f3.x; a[7] += f3.y;
}

// ---------------- dtype detection ------------------------------------------
__global__ void k_flags_init() {
    if (threadIdx.x == 0) { g_nz_ei = 0u; g_nz_batch = 0u; }
}
__global__ void k_detect(const unsigned* __restrict__ p, long long n, int which) {
    unsigned acc = 0;
    for (long long i = blockIdx.x * blockDim.x + threadIdx.x; i < n;
         i += (long long)gridDim.x * blockDim.x)
        acc |= p[2 * i + 1];
    acc |= __shfl_xor_sync(0xffffffffu, acc, 16);
    acc |= __shfl_xor_sync(0xffffffffu, acc, 8);
    acc |= __shfl_xor_sync(0xffffffffu, acc, 4);
    acc |= __shfl_xor_sync(0xffffffffu, acc, 2);
    acc |= __shfl_xor_sync(0xffffffffu, acc, 1);
    if ((threadIdx.x & 31) == 0 && acc) {
        if (which == 0) atomicOr(&g_nz_ei, acc);
        else            atomicOr(&g_nz_batch, acc);
    }
}

// ---------------- setup kernels --------------------------------------------
__global__ void k_zero_meta() {
    int i = blockIdx.x * blockDim.x + threadIdx.x;
    if (i <= N_NODESC) g_rowptr[i] = 0;
    if (i < NUM_GRAPHS * DIM) g_gsum[i] = 0.f;
    if (i < NUM_GRAPHS) g_gcnt[i] = 0.f;
}

__global__ void k_count(const int* __restrict__ ei) {
    bool is64 = (g_nz_ei == 0u);
    int e = blockIdx.x * blockDim.x + threadIdx.x;
    if (e < N_EDGESC) {
        int s = idx_at(ei, e, is64);
        atomicAdd(&g_rowptr[s + 1], 1);
    }
}

__global__ void k_scan1() {
    __shared__ int wsum[8];
    int b = blockIdx.x, t = threadIdx.x;
    int base = b * 1024 + t * 4;
    int v0, v1, v2, v3;
    v0 = (base + 0 <= N_NODESC) ? g_rowptr[base + 0] : 0;
    v1 = (base + 1 <= N_NODESC) ? g_rowptr[base + 1] : 0;
    v2 = (base + 2 <= N_NODESC) ? g_rowptr[base + 2] : 0;
    v3 = (base + 3 <= N_NODESC) ? g_rowptr[base + 3] : 0;
    v1 += v0; v2 += v1; v3 += v2;
    int lane = t & 31, w = t >> 5;
    int s = v3;
    #pragma unroll
    for (int o = 1; o < 32; o <<= 1) {
        int n = __shfl_up_sync(0xffffffffu, s, o);
        if (lane >= o) s += n;
    }
    if (lane == 31) wsum[w] = s;
    __syncthreads();
    if (t < 8) {
        int x = wsum[t];
        #pragma unroll
        for (int o = 1; o < 8; o <<= 1) {
            int n = __shfl_up_sync(0x000000ffu, x, o);
            if (t >= o) x += n;
        }
        wsum[t] = x;
    }
    __syncthreads();
    int excl = (w ? wsum[w - 1] : 0) + (s - v3);
    v0 += excl; v1 += excl; v2 += excl; v3 += excl;
    if (base + 0 <= N_NODESC) g_rowptr[base + 0] = v0;
    if (base + 1 <= N_NODESC) g_rowptr[base + 1] = v1;
    if (base + 2 <= N_NODESC) g_rowptr[base + 2] = v2;
    if (base + 3 <= N_NODESC) g_rowptr[base + 3] = v3;
    if (t == 0) g_bsum[b] = wsum[7];
}

__global__ void k_scan2() {
    __shared__ int sh[64];
    int t = threadIdx.x;
    sh[t] = (t < SCAN_NB) ? g_bsum[t] : 0;
    __syncthreads();
    for (int o = 1; o < 64; o <<= 1) {
        int a = (t >= o) ? sh[t - o] : 0;
        __syncthreads();
        sh[t] += a;
        __syncthreads();
    }
    g_bsum[t] = sh[t];
}

__global__ void k_scan3() {
    int b = blockIdx.x, t = threadIdx.x;
    int add = b ? g_bsum[b - 1] : 0;
    int base = b * 1024 + t * 4;
    #pragma unroll
    for (int i = 0; i < 4; ++i) {
        int idx = base + i;
        if (idx <= N_NODESC) {
            int r = g_rowptr[idx] + add;
            g_rowptr[idx] = r;
            if (idx < N_NODESC) g_fill[idx] = r;
        }
    }
}

__global__ void k_scatter(const int* __restrict__ ei) {
    bool is64 = (g_nz_ei == 0u);
    int e = blockIdx.x * blockDim.x + threadIdx.x;
    if (e < N_EDGESC) {
        int s = idx_at(ei, e, is64);
        int d = idx_at(ei, (long long)N_EDGESC + e, is64);
        int pos = atomicAdd(&g_fill[s], 1);
        g_csr[pos] = d;
    }
}

__global__ void k_hash(const float* __restrict__ Hm, int l) {
    int i = blockIdx.x * blockDim.x + threadIdx.x;
    if (i >= 4 * DIM) return;
    const float* row = Hm + (size_t)i * 128;
    int col = 0; float sgn = 0.f;
    for (int c = 0; c < 128; ++c) {
        float v = row[c];
        if (v != 0.f) { col = c; sgn = v; }
    }
    g_hcol[l][i] = col;
    g_hsign[l][i] = sgn;
}

// g_Wh[l][n=j][k=r] = fp16( cat(Ws, Wp_eff)[r][j] )
__global__ void k_buildW(const float* __restrict__ Wp, const float* __restrict__ Ws, int l) {
    int idx = blockIdx.x * blockDim.x + threadIdx.x;
    if (idx >= KTOT * DIM) return;
    int r = idx >> 9;        // k
    int j = idx & 511;       // n
    float w;
    if (r < 512) {
        w = Ws[r * DIM + j];
    } else {
        int d = r - 512;
        w = 0.f;
        #pragma unroll
        for (int k = 0; k < 4; ++k) {
            int c = g_hcol[l][k * DIM + d];
            w += g_hsign[l][k * DIM + d] * Wp[(size_t)(k * 128 + c) * DIM + j];
        }
    }
    __half h = __float2half_rn(w);
    g_Wh[l][(size_t)j * KTOT + r] = *reinterpret_cast<u16*>(&h);
}

// x -> fp16 plane
__global__ void k_copy_x(const float* __restrict__ x) {
    int i = blockIdx.x * blockDim.x + threadIdx.x;   // float4 index
    if (i >= N_NODESC * (DIM / 4)) return;
    size_t off = (size_t)i * 4;
    float4 v = *(const float4*)(x + off);
    uint2 p;
    p.x = pack2h(v.x, v.y);
    p.y = pack2h(v.z, v.w);
    *(uint2*)(g_xh + off) = p;
}

// ---------------- aggregation: gather-mean over fp16 plane -------------------
// 64 threads per node (16B each), 4 nodes per 256-thread block, 2-edge unroll
__global__ void __launch_bounds__(256)
k_agg(const u16* __restrict__ h, u16* __restrict__ agg) {
    int n = blockIdx.x * 4 + (threadIdx.x >> 6);
    if (n >= N_NODESC) return;
    int t = threadIdx.x & 63;
    int s = g_rowptr[n], e = g_rowptr[n + 1];
    size_t off = (size_t)n * DIM + t * 8;
    uint4 o;
    if (e == s) {
        o = *(const uint4*)(h + off);    // exact self-copy
    } else {
        float a[8] = {0.f, 0.f, 0.f, 0.f, 0.f, 0.f, 0.f, 0.f};
        int j = s;
        for (; j + 2 <= e; j += 2) {
            int d0 = g_csr[j], d1 = g_csr[j + 1];
            uint4 v0 = *(const uint4*)(h + (size_t)d0 * DIM + t * 8);
            uint4 v1 = *(const uint4*)(h + (size_t)d1 * DIM + t * 8);
            acc8(a, v0);
            acc8(a, v1);
        }
        if (j < e) {
            uint4 v = *(const uint4*)(h + (size_t)g_csr[j] * DIM + t * 8);
            acc8(a, v);
        }
        float inv = 1.f / (float)(e - s);
        o.x = pack2h(a[0] * inv, a[1] * inv);
        o.y = pack2h(a[2] * inv, a[3] * inv);
        o.z = pack2h(a[4] * inv, a[5] * inv);
        o.w = pack2h(a[6] * inv, a[7] * inv);
    }
    *(uint4*)(agg + off) = o;
}

// ---------------- fp16 GEMM: out = elu([h|agg] @ W + b) ----------------------
// BM=128, BN=128, BK=32 halves, 3-stage cp.async pipeline, ldmatrix fragments.
#define AWB      80                      // bytes per smem row
#define PLANEB   (128 * AWB)             // 10240 bytes
#define STAGEB   (2 * PLANEB)            // 20480 bytes
#define NSTAGE   3
#define GEMM_SMEM (NSTAGE * STAGEB)      // 61440 bytes

__global__ void __launch_bounds__(256, 2)
k_gemmh(const u16* __restrict__ Hh, const u16* __restrict__ Gh,
        const u16* __restrict__ W, const float* __restrict__ bias,
        u16* __restrict__ C16)
{
    extern __shared__ char S[];
    const u32 sb   = smem_u32(S);
    const int tid  = threadIdx.x;
    const int lane = tid & 31;
    const int wid  = tid >> 5;
    const int g    = lane >> 2;
    const int t4   = lane & 3;
    const int wm   = (wid & 1) * 64;
    const int wn   = (wid >> 1) * 32;
    const int m0   = blockIdx.y * 128;
    const int n0   = blockIdx.x * 128;

    float acc[4][4][4];
    #pragma unroll
    for (int i = 0; i < 4; ++i)
        #pragma unroll
        for (int j = 0; j < 4; ++j)
            #pragma unroll
            for (int k = 0; k < 4; ++k) acc[i][j][k] = 0.f;

    const int qr = tid >> 2;     // 0..63 (row base for chunk loads)
    const int qc = tid & 3;      // 16B chunk within row

    auto load_stage = [&](int kt) {
        const int st = kt % NSTAGE;
        const int kk = kt * 32;
        const u16* Asrc = (kk & 512) ? Gh : Hh;
        const int kc = kk & 511;
        const u32 ab = sb + st * STAGEB;
        #pragma unroll
        for (int i = 0; i < 2; ++i) {
            int row = qr + i * 64;
            int grow = m0 + row;
            int ok = (grow < N_NODESC) ? 16 : 0;
            const u16* src = Asrc + (size_t)(grow < N_NODESC ? grow : 0) * DIM + kc + qc * 8;
            cp16z(ab + row * AWB + qc * 16, src, ok);
        }
        const u32 bb = sb + st * STAGEB + PLANEB;
        #pragma unroll
        for (int i = 0; i < 2; ++i) {
            int row = qr + i * 64;
            const u16* src = W + (size_t)(n0 + row) * KTOT + kk + qc * 8;
            cp16(bb + row * AWB + qc * 16, src);
        }
        asm volatile("cp.async.commit_group;\n");
    };

    load_stage(0);
    load_stage(1);
    load_stage(2);

    // ldmatrix address components
    const u32 a_row  = wm + (lane & 15);
    const u32 a_koff = (lane >> 4) << 4;
    const u32 b_row  = wn + ((lane >> 4) << 3) + (lane & 7);
    const u32 b_koff = ((lane >> 3) & 1) << 4;

    const int KT = KTOT / 32;   // 32
    for (int kt = 0; kt < KT; ++kt) {
        const int st = kt % NSTAGE;
        asm volatile("cp.async.wait_group 2;\n");
        __syncthreads();
        const u32 ab = sb + st * STAGEB;
        const u32 bb = ab + PLANEB;
        #pragma unroll
        for (int ks2 = 0; ks2 < 2; ++ks2) {
            const u32 ko = ks2 << 5;
            u32 a[4][4], b[4][2];
            #pragma unroll
            for (int mi = 0; mi < 4; ++mi)
                ldm_x4(a[mi][0], a[mi][1], a[mi][2], a[mi][3],
                       ab + (a_row + mi * 16) * AWB + a_koff + ko);
            #pragma unroll
            for (int nip = 0; nip < 2; ++nip)
                ldm_x4(b[nip * 2][0], b[nip * 2][1], b[nip * 2 + 1][0], b[nip * 2 + 1][1],
                       bb + (b_row + nip * 16) * AWB + b_koff + ko);
            #pragma unroll
            for (int mi = 0; mi < 4; ++mi)
                #pragma unroll
                for (int ni = 0; ni < 4; ++ni)
                    mma_f16(acc[mi][ni], a[mi], b[ni]);
        }
        __syncthreads();
        if (kt + NSTAGE < KT) load_stage(kt + NSTAGE);
        else asm volatile("cp.async.commit_group;\n");   // keep wait_group count valid
    }

    // epilogue: bias + elu -> fp16 plane
    #pragma unroll
    for (int mi = 0; mi < 4; ++mi) {
        int rr0 = m0 + wm + mi * 16 + g;
        #pragma unroll
        for (int ni = 0; ni < 4; ++ni) {
            int col = n0 + wn + ni * 8 + 2 * t4;
            float bb0 = bias[col], bb1 = bias[col + 1];
            #pragma unroll
            for (int half = 0; half < 2; ++half) {
                int row = rr0 + half * 8;
                if (row < N_NODESC) {
                    float vx = eluf(acc[mi][ni][half * 2 + 0] + bb0);
                    float vy = eluf(acc[mi][ni][half * 2 + 1] + bb1);
                    *(u32*)(C16 + (size_t)row * DIM + col) = pack2h(vx, vy);
                }
            }
        }
    }
}

// ---------------- pooling + classifier --------------------------------------
__global__ void k_pool(const u16* __restrict__ h, const int* __restrict__ batch) {
    bool is64 = (g_nz_batch == 0u);
    int d  = blockIdx.y * 128 + threadIdx.x;
    int n0 = blockIdx.x * 128;
    int ne = min(n0 + 128, N_NODESC);
    int cur = idx_at(batch, n0, is64);
    float acc = 0.f;
    for (int n = n0; n < ne; ++n) {
        int b = idx_at(batch, n, is64);
        if (b != cur) { atomicAdd(&g_gsum[cur * DIM + d], acc); acc = 0.f; cur = b; }
        acc += __half2float(*reinterpret_cast<const __half*>(h + (size_t)n * DIM + d));
    }
    atomicAdd(&g_gsum[cur * DIM + d], acc);
}

__global__ void k_cnt(const int* __restrict__ batch) {
    bool is64 = (g_nz_batch == 0u);
    int n = blockIdx.x * blockDim.x + threadIdx.x;
    if (n < N_NODESC) atomicAdd(&g_gcnt[idx_at(batch, n, is64)], 1.f);
}

__global__ void k_cls(const float* __restrict__ Wc, const float* __restrict__ bc,
                      float* __restrict__ out) {
    int gid = blockIdx.x;
    int t = threadIdx.x;
    __shared__ float gv[DIM];
    __shared__ float red[NUM_CLASSES][128];
    float inv = 1.f / fmaxf(g_gcnt[gid], 1.f);
    for (int d = t; d < DIM; d += 128) gv[d] = g_gsum[gid * DIM + d] * inv;
    __syncthreads();
    float p[NUM_CLASSES];
    #pragma unroll
    for (int c = 0; c < NUM_CLASSES; ++c) p[c] = 0.f;
    for (int d = t; d < DIM; d += 128) {
        float v = gv[d];
        #pragma unroll
        for (int c = 0; c < NUM_CLASSES; ++c) p[c] += v * Wc[d * NUM_CLASSES + c];
    }
    #pragma unroll
    for (int c = 0; c < NUM_CLASSES; ++c) red[c][t] = p[c];
    __syncthreads();
    for (int off = 64; off > 0; off >>= 1) {
        if (t < off)
            #pragma unroll
            for (int c = 0; c < NUM_CLASSES; ++c) red[c][t] += red[c][t + off];
        __syncthreads();
    }
    if (t < NUM_CLASSES) out[gid * NUM_CLASSES + t] = red[t][0] + bc[t];
}

// ---------------- launch -----------------------------------------------------
extern "C" void kernel_launch(void* const* d_in, const int* in_sizes, int n_in,
                              void* d_out, int out_size) {
    const float* x     = (const float*)d_in[0];
    const int*   ei    = (const int*)d_in[1];
    const int*   batch = (const int*)d_in[2];
    const float* Hm1   = (const float*)d_in[3];
    const float* Wp1   = (const float*)d_in[4];
    const float* Ws1   = (const float*)d_in[5];
    const float* b1    = (const float*)d_in[6];
    const float* Hm2   = (const float*)d_in[7];
    const float* Wp2   = (const float*)d_in[8];
    const float* Ws2   = (const float*)d_in[9];
    const float* b2    = (const float*)d_in[10];
    const float* Wc    = (const float*)d_in[11];
    const float* bc    = (const float*)d_in[12];
    float*       out   = (float*)d_out;

    u16 *xh, *agh, *h1h, *h2h, *wh;
    cudaGetSymbolAddress((void**)&xh,  g_xh);
    cudaGetSymbolAddress((void**)&agh, g_agh);
    cudaGetSymbolAddress((void**)&h1h, g_h1h);
    cudaGetSymbolAddress((void**)&h2h, g_h2h);
    cudaGetSymbolAddress((void**)&wh,  g_Wh);
    u16* W0 = wh;
    u16* W1 = wh + (size_t)DIM * KTOT;

    cudaFuncSetAttribute(k_gemmh, cudaFuncAttributeMaxDynamicSharedMemorySize, GEMM_SMEM);

    // dtype detection
    k_flags_init<<<1, 32>>>();
    k_detect<<<256, 256>>>((const unsigned*)ei, N_EDGESC, 0);
    k_detect<<<64, 256>>>((const unsigned*)batch, N_NODESC / 2, 1);

    // setup
    k_zero_meta<<<196, 256>>>();
    k_count<<<(N_EDGESC + 255) / 256, 256>>>(ei);
    k_scan1<<<SCAN_NB, 256>>>();
    k_scan2<<<1, 64>>>();
    k_scan3<<<SCAN_NB, 256>>>();
    k_scatter<<<(N_EDGESC + 255) / 256, 256>>>(ei);
    k_hash<<<8, 256>>>(Hm1, 0);
    k_hash<<<8, 256>>>(Hm2, 1);
    k_buildW<<<(KTOT * DIM + 255) / 256, 256>>>(Wp1, Ws1, 0);
    k_buildW<<<(KTOT * DIM + 255) / 256, 256>>>(Wp2, Ws2, 1);
    k_copy_x<<<(N_NODESC * (DIM / 4) + 255) / 256, 256>>>(x);

    dim3 ggrid(DIM / 128, (N_NODESC + 127) / 128);   // (4, 391)
    int aggrid = (N_NODESC + 3) / 4;                 // 12500

    // layer 1
    k_agg<<<aggrid, 256>>>(xh, agh);
    k_gemmh<<<ggrid, 256, GEMM_SMEM>>>(xh, agh, W0, b1, h1h);

    // layer 2
    k_agg<<<aggrid, 256>>>(h1h, agh);
    k_gemmh<<<ggrid, 256, GEMM_SMEM>>>(h1h, agh, W1, b2, h2h);

    // pool + classify
    k_pool<<<dim3((N_NODESC + 127) / 128, 4), 128>>>(h2h, batch);
    k_cnt<<<196, 256>>>(batch);
    k_cls<<<NUM_GRAPHS, 128>>>(Wc, bc, out);
}

// round 9
// speedup vs baseline: 2.2799x; 1.1274x over previous
#include <cuda_runtime.h>
#include <cuda_fp16.h>
#include <cstdint>
#include <math.h>

#define N_NODESC   50000
#define N_EDGESC   800000
#define DIM        512
#define KTOT       1024
#define NUM_GRAPHS 64
#define NUM_CLASSES 10
#define SCAN_NB    ((N_NODESC + 1 + 1023) / 1024)   // 49

typedef unsigned short u16;
typedef unsigned int   u32;

// ---------------- scratch (device globals; no allocation allowed) ----------
__device__ __align__(16) u16   g_xh [(size_t)N_NODESC * DIM];   // x, fp16
__device__ __align__(16) u16   g_agh[(size_t)N_NODESC * DIM];   // agg, fp16
__device__ __align__(16) u16   g_h1h[(size_t)N_NODESC * DIM];   // h1, fp16
__device__ __align__(16) u16   g_h2h[(size_t)N_NODESC * DIM];   // h2, fp16
__device__ __align__(16) u16   g_Wh [2][(size_t)DIM * KTOT];    // [layer][n][k], fp16
__device__ int   g_rowptr[N_NODESC + 1];
__device__ int   g_fill  [N_NODESC];
__device__ int   g_csr   [N_EDGESC];
__device__ int   g_hcol [2][4 * DIM];
__device__ float g_hsign[2][4 * DIM];
__device__ float g_gsum[NUM_GRAPHS * DIM];
__device__ float g_gcnt[NUM_GRAPHS];
__device__ int   g_bsum[64];
__device__ unsigned g_nz_ei = 0;      // static zero init; detect only ORs (idempotent)
__device__ unsigned g_nz_batch = 0;

// ---------------- helpers ---------------------------------------------------
__device__ __forceinline__ float eluf(float x) { return x > 0.f ? x : expm1f(x); }

__device__ __forceinline__ int idx_at(const int* p, long long i, bool is64) {
    return is64 ? p[2 * i] : p[i];
}

__device__ __forceinline__ void mma_f16(float* d, const u32* a, const u32* b) {
    asm volatile(
        "mma.sync.aligned.m16n8k16.row.col.f32.f16.f16.f32 "
        "{%0,%1,%2,%3},{%4,%5,%6,%7},{%8,%9},{%0,%1,%2,%3};\n"
        : "+f"(d[0]), "+f"(d[1]), "+f"(d[2]), "+f"(d[3])
        : "r"(a[0]), "r"(a[1]), "r"(a[2]), "r"(a[3]), "r"(b[0]), "r"(b[1]));
}
__device__ __forceinline__ void ldm_x4(u32& r0, u32& r1, u32& r2, u32& r3, u32 addr) {
    asm volatile("ldmatrix.sync.aligned.m8n8.x4.shared.b16 {%0,%1,%2,%3}, [%4];"
                 : "=r"(r0), "=r"(r1), "=r"(r2), "=r"(r3) : "r"(addr));
}
__device__ __forceinline__ void cp16(u32 dst, const void* src) {
    asm volatile("cp.async.cg.shared.global [%0], [%1], 16;\n" :: "r"(dst), "l"(src));
}
__device__ __forceinline__ void cp16z(u32 dst, const void* src, int nbytes) {
    asm volatile("cp.async.cg.shared.global [%0], [%1], 16, %2;\n"
                 :: "r"(dst), "l"(src), "r"(nbytes));
}
__device__ __forceinline__ u32 smem_u32(const void* p) {
    u32 a;
    asm("{ .reg .u64 t; cvta.to.shared.u64 t, %1; cvt.u32.u64 %0, t; }" : "=r"(a) : "l"(p));
    return a;
}
__device__ __forceinline__ u32 pack2h(float a, float b) {
    __half2 h = __floats2half2_rn(a, b);
    return *reinterpret_cast<u32*>(&h);
}
__device__ __forceinline__ void acc8(float* a, uint4 v) {
    float2 f0 = __half22float2(*reinterpret_cast<__half2*>(&v.x));
    float2 f1 = __half22float2(*reinterpret_cast<__half2*>(&v.y));
    float2 f2 = __half22float2(*reinterpret_cast<__half2*>(&v.z));
    float2 f3 = __half22float2(*reinterpret_cast<__half2*>(&v.w));
    a[0] += f0.x; a[1] += f0.y; a[2] += f1.x; a[3] += f1.y;
    a[4] += f2.x; a[5] += f2.y; a[6] += f3.x; a[7] += f3.y;
}

// ---------------- dtype detection ------------------------------------------
__global__ void k_detect(const unsigned* __restrict__ p, long long n, int which) {
    unsigned acc = 0;
    for (long long i = blockIdx.x * blockDim.x + threadIdx.x; i < n;
         i += (long long)gridDim.x * blockDim.x)
        acc |= p[2 * i + 1];
    acc |= __shfl_xor_sync(0xffffffffu, acc, 16);
    acc |= __shfl_xor_sync(0xffffffffu, acc, 8);
    acc |= __shfl_xor_sync(0xffffffffu, acc, 4);
    acc |= __shfl_xor_sync(0xffffffffu, acc, 2);
    acc |= __shfl_xor_sync(0xffffffffu, acc, 1);
    if ((threadIdx.x & 31) == 0 && acc) {
        if (which == 0) atomicOr(&g_nz_ei, acc);
        else            atomicOr(&g_nz_batch, acc);
    }
}

// ---------------- setup kernels --------------------------------------------
__global__ void k_zero_meta() {
    int i = blockIdx.x * blockDim.x + threadIdx.x;
    if (i <= N_NODESC) g_rowptr[i] = 0;
    if (i < NUM_GRAPHS * DIM) g_gsum[i] = 0.f;
    if (i < NUM_GRAPHS) g_gcnt[i] = 0.f;
}

__global__ void k_count(const int* __restrict__ ei) {
    bool is64 = (g_nz_ei == 0u);
    int e = blockIdx.x * blockDim.x + threadIdx.x;
    if (e < N_EDGESC) {
        int s = idx_at(ei, e, is64);
        atomicAdd(&g_rowptr[s + 1], 1);
    }
}

__global__ void k_scan1() {
    __shared__ int wsum[8];
    int b = blockIdx.x, t = threadIdx.x;
    int base = b * 1024 + t * 4;
    int v0, v1, v2, v3;
    v0 = (base + 0 <= N_NODESC) ? g_rowptr[base + 0] : 0;
    v1 = (base + 1 <= N_NODESC) ? g_rowptr[base + 1] : 0;
    v2 = (base + 2 <= N_NODESC) ? g_rowptr[base + 2] : 0;
    v3 = (base + 3 <= N_NODESC) ? g_rowptr[base + 3] : 0;
    v1 += v0; v2 += v1; v3 += v2;
    int lane = t & 31, w = t >> 5;
    int s = v3;
    #pragma unroll
    for (int o = 1; o < 32; o <<= 1) {
        int n = __shfl_up_sync(0xffffffffu, s, o);
        if (lane >= o) s += n;
    }
    if (lane == 31) wsum[w] = s;
    __syncthreads();
    if (t < 8) {
        int x = wsum[t];
        #pragma unroll
        for (int o = 1; o < 8; o <<= 1) {
            int n = __shfl_up_sync(0x000000ffu, x, o);
            if (t >= o) x += n;
        }
        wsum[t] = x;
    }
    __syncthreads();
    int excl = (w ? wsum[w - 1] : 0) + (s - v3);
    v0 += excl; v1 += excl; v2 += excl; v3 += excl;
    if (base + 0 <= N_NODESC) g_rowptr[base + 0] = v0;
    if (base + 1 <= N_NODESC) g_rowptr[base + 1] = v1;
    if (base + 2 <= N_NODESC) g_rowptr[base + 2] = v2;
    if (base + 3 <= N_NODESC) g_rowptr[base + 3] = v3;
    if (t == 0) g_bsum[b] = wsum[7];
}

__global__ void k_scan2() {
    __shared__ int sh[64];
    int t = threadIdx.x;
    sh[t] = (t < SCAN_NB) ? g_bsum[t] : 0;
    __syncthreads();
    for (int o = 1; o < 64; o <<= 1) {
        int a = (t >= o) ? sh[t - o] : 0;
        __syncthreads();
        sh[t] += a;
        __syncthreads();
    }
    g_bsum[t] = sh[t];
}

__global__ void k_scan3() {
    int b = blockIdx.x, t = threadIdx.x;
    int add = b ? g_bsum[b - 1] : 0;
    int base = b * 1024 + t * 4;
    #pragma unroll
    for (int i = 0; i < 4; ++i) {
        int idx = base + i;
        if (idx <= N_NODESC) {
            int r = g_rowptr[idx] + add;
            g_rowptr[idx] = r;
            if (idx < N_NODESC) g_fill[idx] = r;
        }
    }
}

__global__ void k_scatter(const int* __restrict__ ei) {
    bool is64 = (g_nz_ei == 0u);
    int e = blockIdx.x * blockDim.x + threadIdx.x;
    if (e < N_EDGESC) {
        int s = idx_at(ei, e, is64);
        int d = idx_at(ei, (long long)N_EDGESC + e, is64);
        int pos = atomicAdd(&g_fill[s], 1);
        g_csr[pos] = d;
    }
}

// one warp per hash row: coalesced scan + ballot pick
__global__ void k_hash(const float* __restrict__ Hm, int l) {
    int warp = (blockIdx.x * blockDim.x + threadIdx.x) >> 5;
    int lane = threadIdx.x & 31;
    if (warp >= 4 * DIM) return;
    const float* row = Hm + (size_t)warp * 128;
    int col = 0; float sgn = 0.f;
    #pragma unroll
    for (int i = 0; i < 4; ++i) {
        float v = row[lane + i * 32];
        if (v != 0.f) { col = lane + i * 32; sgn = v; }
    }
    unsigned m = __ballot_sync(0xffffffffu, sgn != 0.f);
    if (m) {
        int src = __ffs(m) - 1;
        col = __shfl_sync(0xffffffffu, col, src);
        sgn = __shfl_sync(0xffffffffu, sgn, src);
    }
    if (lane == 0) { g_hcol[l][warp] = col; g_hsign[l][warp] = sgn; }
}

// g_Wh[l][n=j][k=r] = fp16( cat(Ws, Wp_eff)[r][j] )
__global__ void k_buildW(const float* __restrict__ Wp, const float* __restrict__ Ws, int l) {
    int idx = blockIdx.x * blockDim.x + threadIdx.x;
    if (idx >= KTOT * DIM) return;
    int r = idx >> 9;        // k
    int j = idx & 511;       // n
    float w;
    if (r < 512) {
        w = Ws[r * DIM + j];
    } else {
        int d = r - 512;
        w = 0.f;
        #pragma unroll
        for (int k = 0; k < 4; ++k) {
            int c = g_hcol[l][k * DIM + d];
            w += g_hsign[l][k * DIM + d] * Wp[(size_t)(k * 128 + c) * DIM + j];
        }
    }
    __half h = __float2half_rn(w);
    g_Wh[l][(size_t)j * KTOT + r] = *reinterpret_cast<u16*>(&h);
}

// x -> fp16 plane
__global__ void k_copy_x(const float* __restrict__ x) {
    int i = blockIdx.x * blockDim.x + threadIdx.x;   // float4 index
    if (i >= N_NODESC * (DIM / 4)) return;
    size_t off = (size_t)i * 4;
    float4 v = *(const float4*)(x + off);
    uint2 p;
    p.x = pack2h(v.x, v.y);
    p.y = pack2h(v.z, v.w);
    *(uint2*)(g_xh + off) = p;
}

// ---------------- aggregation: gather-mean over fp16 plane -------------------
__global__ void __launch_bounds__(256)
k_agg(const u16* __restrict__ h, u16* __restrict__ agg) {
    int n = blockIdx.x * 4 + (threadIdx.x >> 6);
    if (n >= N_NODESC) return;
    int t = threadIdx.x & 63;
    int s = g_rowptr[n], e = g_rowptr[n + 1];
    size_t off = (size_t)n * DIM + t * 8;
    uint4 o;
    if (e == s) {
        o = *(const uint4*)(h + off);
    } else {
        float a[8] = {0.f, 0.f, 0.f, 0.f, 0.f, 0.f, 0.f, 0.f};
        int j = s;
        for (; j + 2 <= e; j += 2) {
            int d0 = g_csr[j], d1 = g_csr[j + 1];
            uint4 v0 = *(const uint4*)(h + (size_t)d0 * DIM + t * 8);
            uint4 v1 = *(const uint4*)(h + (size_t)d1 * DIM + t * 8);
            acc8(a, v0);
            acc8(a, v1);
        }
        if (j < e) {
            uint4 v = *(const uint4*)(h + (size_t)g_csr[j] * DIM + t * 8);
            acc8(a, v);
        }
        float inv = 1.f / (float)(e - s);
        o.x = pack2h(a[0] * inv, a[1] * inv);
        o.y = pack2h(a[2] * inv, a[3] * inv);
        o.z = pack2h(a[4] * inv, a[5] * inv);
        o.w = pack2h(a[6] * inv, a[7] * inv);
    }
    *(uint4*)(agg + off) = o;
}

// ---------------- fp16 GEMM: out = elu([h|agg] @ W + b) ----------------------
// BM=128, BN=128, BK=32 halves, 4-stage cp.async ring, one sync per slab.
#define AWB      80                      // bytes per smem row
#define PLANEB   (128 * AWB)             // 10240 bytes
#define STAGEB   (2 * PLANEB)            // 20480 bytes
#define NSTAGE   4
#define GEMM_SMEM (NSTAGE * STAGEB)      // 81920 bytes

__global__ void __launch_bounds__(256, 2)
k_gemmh(const u16* __restrict__ Hh, const u16* __restrict__ Gh,
        const u16* __restrict__ W, const float* __restrict__ bias,
        u16* __restrict__ C16)
{
    extern __shared__ char S[];
    const u32 sb   = smem_u32(S);
    const int tid  = threadIdx.x;
    const int lane = tid & 31;
    const int wid  = tid >> 5;
    const int g    = lane >> 2;
    const int t4   = lane & 3;
    const int wm   = (wid & 1) * 64;
    const int wn   = (wid >> 1) * 32;
    const int m0   = blockIdx.y * 128;
    const int n0   = blockIdx.x * 128;

    float acc[4][4][4];
    #pragma unroll
    for (int i = 0; i < 4; ++i)
        #pragma unroll
        for (int j = 0; j < 4; ++j)
            #pragma unroll
            for (int k = 0; k < 4; ++k) acc[i][j][k] = 0.f;

    const int qr = tid >> 2;     // 0..63
    const int qc = tid & 3;      // 16B chunk within row

    auto load_stage = [&](int kt) {
        const int st = kt & (NSTAGE - 1);
        const int kk = kt * 32;
        const u16* Asrc = (kk & 512) ? Gh : Hh;
        const int kc = kk & 511;
        const u32 ab = sb + st * STAGEB;
        #pragma unroll
        for (int i = 0; i < 2; ++i) {
            int row = qr + i * 64;
            int grow = m0 + row;
            int ok = (grow < N_NODESC) ? 16 : 0;
            const u16* src = Asrc + (size_t)(grow < N_NODESC ? grow : 0) * DIM + kc + qc * 8;
            cp16z(ab + row * AWB + qc * 16, src, ok);
        }
        const u32 bb = sb + st * STAGEB + PLANEB;
        #pragma unroll
        for (int i = 0; i < 2; ++i) {
            int row = qr + i * 64;
            const u16* src = W + (size_t)(n0 + row) * KTOT + kk + qc * 8;
            cp16(bb + row * AWB + qc * 16, src);
        }
        asm volatile("cp.async.commit_group;\n");
    };

    load_stage(0);
    load_stage(1);
    load_stage(2);

    const u32 a_row  = wm + (lane & 15);
    const u32 a_koff = (lane >> 4) << 4;
    const u32 b_row  = wn + ((lane >> 4) << 3) + (lane & 7);
    const u32 b_koff = ((lane >> 3) & 1) << 4;

    const int KT = KTOT / 32;   // 32
    for (int kt = 0; kt < KT; ++kt) {
        const int st = kt & (NSTAGE - 1);
        asm volatile("cp.async.wait_group 2;\n");
        __syncthreads();
        // issue next load BEFORE compute (distinct ring slot; prev reader synced)
        if (kt + 3 < KT) load_stage(kt + 3);
        else asm volatile("cp.async.commit_group;\n");   // keep group count valid
        const u32 ab = sb + st * STAGEB;
        const u32 bb = ab + PLANEB;
        #pragma unroll
        for (int ks2 = 0; ks2 < 2; ++ks2) {
            const u32 ko = ks2 << 5;
            u32 a[4][4], b[4][2];
            #pragma unroll
            for (int mi = 0; mi < 4; ++mi)
                ldm_x4(a[mi][0], a[mi][1], a[mi][2], a[mi][3],
                       ab + (a_row + mi * 16) * AWB + a_koff + ko);
            #pragma unroll
            for (int nip = 0; nip < 2; ++nip)
                ldm_x4(b[nip * 2][0], b[nip * 2][1], b[nip * 2 + 1][0], b[nip * 2 + 1][1],
                       bb + (b_row + nip * 16) * AWB + b_koff + ko);
            #pragma unroll
            for (int mi = 0; mi < 4; ++mi)
                #pragma unroll
                for (int ni = 0; ni < 4; ++ni)
                    mma_f16(acc[mi][ni], a[mi], b[ni]);
        }
    }

    // epilogue: bias + elu -> fp16 plane
    #pragma unroll
    for (int mi = 0; mi < 4; ++mi) {
        int rr0 = m0 + wm + mi * 16 + g;
        #pragma unroll
        for (int ni = 0; ni < 4; ++ni) {
            int col = n0 + wn + ni * 8 + 2 * t4;
            float bb0 = bias[col], bb1 = bias[col + 1];
            #pragma unroll
            for (int half = 0; half < 2; ++half) {
                int row = rr0 + half * 8;
                if (row < N_NODESC) {
                    float vx = eluf(acc[mi][ni][half * 2 + 0] + bb0);
                    float vy = eluf(acc[mi][ni][half * 2 + 1] + bb1);
                    *(u32*)(C16 + (size_t)row * DIM + col) = pack2h(vx, vy);
                }
            }
        }
    }
}

// ---------------- pooling + classifier --------------------------------------
__global__ void k_pool(const u16* __restrict__ h, const int* __restrict__ batch) {
    bool is64 = (g_nz_batch == 0u);
    int d  = blockIdx.y * 128 + threadIdx.x;
    int n0 = blockIdx.x * 128;
    int ne = min(n0 + 128, N_NODESC);
    int cur = idx_at(batch, n0, is64);
    float acc = 0.f;
    for (int n = n0; n < ne; ++n) {
        int b = idx_at(batch, n, is64);
        if (b != cur) { atomicAdd(&g_gsum[cur * DIM + d], acc); acc = 0.f; cur = b; }
        acc += __half2float(*reinterpret_cast<const __half*>(h + (size_t)n * DIM + d));
    }
    atomicAdd(&g_gsum[cur * DIM + d], acc);
}

__global__ void k_cnt(const int* __restrict__ batch) {
    __shared__ int hist[NUM_GRAPHS];
    int t = threadIdx.x;
    if (t < NUM_GRAPHS) hist[t] = 0;
    __syncthreads();
    bool is64 = (g_nz_batch == 0u);
    int n = blockIdx.x * blockDim.x + t;
    if (n < N_NODESC) atomicAdd(&hist[idx_at(batch, n, is64)], 1);
    __syncthreads();
    if (t < NUM_GRAPHS && hist[t]) atomicAdd(&g_gcnt[t], (float)hist[t]);
}

__global__ void k_cls(const float* __restrict__ Wc, const float* __restrict__ bc,
                      float* __restrict__ out) {
    int gid = blockIdx.x;
    int t = threadIdx.x;
    __shared__ float gv[DIM];
    __shared__ float red[NUM_CLASSES][128];
    float inv = 1.f / fmaxf(g_gcnt[gid], 1.f);
    for (int d = t; d < DIM; d += 128) gv[d] = g_gsum[gid * DIM + d] * inv;
    __syncthreads();
    float p[NUM_CLASSES];
    #pragma unroll
    for (int c = 0; c < NUM_CLASSES; ++c) p[c] = 0.f;
    for (int d = t; d < DIM; d += 128) {
        float v = gv[d];
        #pragma unroll
        for (int c = 0; c < NUM_CLASSES; ++c) p[c] += v * Wc[d * NUM_CLASSES + c];
    }
    #pragma unroll
    for (int c = 0; c < NUM_CLASSES; ++c) red[c][t] = p[c];
    __syncthreads();
    for (int off = 64; off > 0; off >>= 1) {
        if (t < off)
            #pragma unroll
            for (int c = 0; c < NUM_CLASSES; ++c) red[c][t] += red[c][t + off];
        __syncthreads();
    }
    if (t < NUM_CLASSES) out[gid * NUM_CLASSES + t] = red[t][0] + bc[t];
}

// ---------------- launch -----------------------------------------------------
extern "C" void kernel_launch(void* const* d_in, const int* in_sizes, int n_in,
                              void* d_out, int out_size) {
    const float* x     = (const float*)d_in[0];
    const int*   ei    = (const int*)d_in[1];
    const int*   batch = (const int*)d_in[2];
    const float* Hm1   = (const float*)d_in[3];
    const float* Wp1   = (const float*)d_in[4];
    const float* Ws1   = (const float*)d_in[5];
    const float* b1    = (const float*)d_in[6];
    const float* Hm2   = (const float*)d_in[7];
    const float* Wp2   = (const float*)d_in[8];
    const float* Ws2   = (const float*)d_in[9];
    const float* b2    = (const float*)d_in[10];
    const float* Wc    = (const float*)d_in[11];
    const float* bc    = (const float*)d_in[12];
    float*       out   = (float*)d_out;

    u16 *xh, *agh, *h1h, *h2h, *wh;
    cudaGetSymbolAddress((void**)&xh,  g_xh);
    cudaGetSymbolAddress((void**)&agh, g_agh);
    cudaGetSymbolAddress((void**)&h1h, g_h1h);
    cudaGetSymbolAddress((void**)&h2h, g_h2h);
    cudaGetSymbolAddress((void**)&wh,  g_Wh);
    u16* W0 = wh;
    u16* W1 = wh + (size_t)DIM * KTOT;

    cudaFuncSetAttribute(k_gemmh, cudaFuncAttributeMaxDynamicSharedMemorySize, GEMM_SMEM);

    // dtype detection (flags statically zero-initialized; OR is idempotent across replays)
    k_detect<<<256, 256>>>((const unsigned*)ei, N_EDGESC, 0);
    k_detect<<<64, 256>>>((const unsigned*)batch, N_NODESC / 2, 1);

    // setup
    k_zero_meta<<<196, 256>>>();
    k_count<<<(N_EDGESC + 255) / 256, 256>>>(ei);
    k_scan1<<<SCAN_NB, 256>>>();
    k_scan2<<<1, 64>>>();
    k_scan3<<<SCAN_NB, 256>>>();
    k_scatter<<<(N_EDGESC + 255) / 256, 256>>>(ei);
    k_hash<<<(4 * DIM * 32 + 255) / 256, 256>>>(Hm1, 0);
    k_hash<<<(4 * DIM * 32 + 255) / 256, 256>>>(Hm2, 1);
    k_buildW<<<(KTOT * DIM + 255) / 256, 256>>>(Wp1, Ws1, 0);
    k_buildW<<<(KTOT * DIM + 255) / 256, 256>>>(Wp2, Ws2, 1);
    k_copy_x<<<(N_NODESC * (DIM / 4) + 255) / 256, 256>>>(x);

    dim3 ggrid(DIM / 128, (N_NODESC + 127) / 128);   // (4, 391)
    int aggrid = (N_NODESC + 3) / 4;                 // 12500

    // layer 1
    k_agg<<<aggrid, 256>>>(xh, agh);
    k_gemmh<<<ggrid, 256, GEMM_SMEM>>>(xh, agh, W0, b1, h1h);

    // layer 2
    k_agg<<<aggrid, 256>>>(h1h, agh);
    k_gemmh<<<ggrid, 256, GEMM_SMEM>>>(h1h, agh, W1, b2, h2h);

    // pool + classify
    k_pool<<<dim3((N_NODESC + 127) / 128, 4), 128>>>(h2h, batch);
    k_cnt<<<196, 256>>>(batch);
    k_cls<<<NUM_GRAPHS, 128>>>(Wc, bc, out);
}

// round 10
// speedup vs baseline: 2.2873x; 1.0032x over previous
#include <cuda_runtime.h>
#include <cuda_fp16.h>
#include <cstdint>
#include <math.h>

#define N_NODESC   50000
#define N_EDGESC   800000
#define DIM        512
#define KTOT       1024
#define NUM_GRAPHS 64
#define NUM_CLASSES 10
#define SCAN_NB    ((N_NODESC + 1 + 1023) / 1024)   // 49

typedef unsigned short u16;
typedef unsigned int   u32;

// ---------------- scratch (device globals; no allocation allowed) ----------
__device__ __align__(16) u16   g_xh [(size_t)N_NODESC * DIM];   // x, fp16
__device__ __align__(16) u16   g_agh[(size_t)N_NODESC * DIM];   // agg, fp16
__device__ __align__(16) u16   g_h1h[(size_t)N_NODESC * DIM];   // h1, fp16
__device__ __align__(16) u16   g_h2h[(size_t)N_NODESC * DIM];   // h2, fp16
__device__ __align__(16) u16   g_Wh [2][(size_t)DIM * KTOT];    // [layer][n][k], fp16
__device__ int   g_rowptr[N_NODESC + 1];
__device__ int   g_fill  [N_NODESC];
__device__ int   g_csr   [N_EDGESC];
__device__ int   g_hcol [2][4 * DIM];
__device__ float g_hsign[2][4 * DIM];
__device__ float g_gsum[NUM_GRAPHS * DIM];
__device__ float g_gcnt[NUM_GRAPHS];
__device__ int   g_bsum[64];
__device__ unsigned g_nz_ei = 0;      // static zero init; detect only ORs (idempotent)
__device__ unsigned g_nz_batch = 0;

// ---------------- helpers ---------------------------------------------------
__device__ __forceinline__ float eluf(float x) { return x > 0.f ? x : expm1f(x); }

__device__ __forceinline__ int idx_at(const int* p, long long i, bool is64) {
    return is64 ? p[2 * i] : p[i];
}

__device__ __forceinline__ void mma_f16(float* d, const u32* a, const u32* b) {
    asm volatile(
        "mma.sync.aligned.m16n8k16.row.col.f32.f16.f16.f32 "
        "{%0,%1,%2,%3},{%4,%5,%6,%7},{%8,%9},{%0,%1,%2,%3};\n"
        : "+f"(d[0]), "+f"(d[1]), "+f"(d[2]), "+f"(d[3])
        : "r"(a[0]), "r"(a[1]), "r"(a[2]), "r"(a[3]), "r"(b[0]), "r"(b[1]));
}
__device__ __forceinline__ void ldm_x4(u32& r0, u32& r1, u32& r2, u32& r3, u32 addr) {
    asm volatile("ldmatrix.sync.aligned.m8n8.x4.shared.b16 {%0,%1,%2,%3}, [%4];"
                 : "=r"(r0), "=r"(r1), "=r"(r2), "=r"(r3) : "r"(addr));
}
__device__ __forceinline__ void cp16(u32 dst, const void* src) {
    asm volatile("cp.async.cg.shared.global [%0], [%1], 16;\n" :: "r"(dst), "l"(src));
}
__device__ __forceinline__ void cp16z(u32 dst, const void* src, int nbytes) {
    asm volatile("cp.async.cg.shared.global [%0], [%1], 16, %2;\n"
                 :: "r"(dst), "l"(src), "r"(nbytes));
}
__device__ __forceinline__ u32 smem_u32(const void* p) {
    u32 a;
    asm("{ .reg .u64 t; cvta.to.shared.u64 t, %1; cvt.u32.u64 %0, t; }" : "=r"(a) : "l"(p));
    return a;
}
__device__ __forceinline__ u32 pack2h(float a, float b) {
    __half2 h = __floats2half2_rn(a, b);
    return *reinterpret_cast<u32*>(&h);
}
__device__ __forceinline__ void acc8(float* a, uint4 v) {
    float2 f0 = __half22float2(*reinterpret_cast<__half2*>(&v.x));
    float2 f1 = __half22float2(*reinterpret_cast<__half2*>(&v.y));
    float2 f2 = __half22float2(*reinterpret_cast<__half2*>(&v.z));
    float2 f3 = __half22float2(*reinterpret_cast<__half2*>(&v.w));
    a[0] += f0.x; a[1] += f0.y; a[2] += f1.x; a[3] += f1.y;
    a[4] += f2.x; a[5] += f2.y; a[6] += f3.x; a[7] += f3.y;
}

// ---------------- dtype detection ------------------------------------------
__global__ void k_detect(const unsigned* __restrict__ p, long long n, int which) {
    unsigned acc = 0;
    for (long long i = blockIdx.x * blockDim.x + threadIdx.x; i < n;
         i += (long long)gridDim.x * blockDim.x)
        acc |= p[2 * i + 1];
    acc |= __shfl_xor_sync(0xffffffffu, acc, 16);
    acc |= __shfl_xor_sync(0xffffffffu, acc, 8);
    acc |= __shfl_xor_sync(0xffffffffu, acc, 4);
    acc |= __shfl_xor_sync(0xffffffffu, acc, 2);
    acc |= __shfl_xor_sync(0xffffffffu, acc, 1);
    if ((threadIdx.x & 31) == 0 && acc) {
        if (which == 0) atomicOr(&g_nz_ei, acc);
        else            atomicOr(&g_nz_batch, acc);
    }
}

// ---------------- setup kernels --------------------------------------------
__global__ void k_zero_meta() {
    int i = blockIdx.x * blockDim.x + threadIdx.x;
    if (i <= N_NODESC) g_rowptr[i] = 0;
    if (i < NUM_GRAPHS * DIM) g_gsum[i] = 0.f;
    if (i < NUM_GRAPHS) g_gcnt[i] = 0.f;
}

__global__ void k_count(const int* __restrict__ ei) {
    bool is64 = (g_nz_ei == 0u);
    int e = blockIdx.x * blockDim.x + threadIdx.x;
    if (e < N_EDGESC) {
        int s = idx_at(ei, e, is64);
        atomicAdd(&g_rowptr[s + 1], 1);
    }
}

__global__ void k_scan1() {
    __shared__ int wsum[8];
    int b = blockIdx.x, t = threadIdx.x;
    int base = b * 1024 + t * 4;
    int v0, v1, v2, v3;
    v0 = (base + 0 <= N_NODESC) ? g_rowptr[base + 0] : 0;
    v1 = (base + 1 <= N_NODESC) ? g_rowptr[base + 1] : 0;
    v2 = (base + 2 <= N_NODESC) ? g_rowptr[base + 2] : 0;
    v3 = (base + 3 <= N_NODESC) ? g_rowptr[base + 3] : 0;
    v1 += v0; v2 += v1; v3 += v2;
    int lane = t & 31, w = t >> 5;
    int s = v3;
    #pragma unroll
    for (int o = 1; o < 32; o <<= 1) {
        int n = __shfl_up_sync(0xffffffffu, s, o);
        if (lane >= o) s += n;
    }
    if (lane == 31) wsum[w] = s;
    __syncthreads();
    if (t < 8) {
        int x = wsum[t];
        #pragma unroll
        for (int o = 1; o < 8; o <<= 1) {
            int n = __shfl_up_sync(0x000000ffu, x, o);
            if (t >= o) x += n;
        }
        wsum[t] = x;
    }
    __syncthreads();
    int excl = (w ? wsum[w - 1] : 0) + (s - v3);
    v0 += excl; v1 += excl; v2 += excl; v3 += excl;
    if (base + 0 <= N_NODESC) g_rowptr[base + 0] = v0;
    if (base + 1 <= N_NODESC) g_rowptr[base + 1] = v1;
    if (base + 2 <= N_NODESC) g_rowptr[base + 2] = v2;
    if (base + 3 <= N_NODESC) g_rowptr[base + 3] = v3;
    if (t == 0) g_bsum[b] = wsum[7];
}

__global__ void k_scan2() {
    __shared__ int sh[64];
    int t = threadIdx.x;
    sh[t] = (t < SCAN_NB) ? g_bsum[t] : 0;
    __syncthreads();
    for (int o = 1; o < 64; o <<= 1) {
        int a = (t >= o) ? sh[t - o] : 0;
        __syncthreads();
        sh[t] += a;
        __syncthreads();
    }
    g_bsum[t] = sh[t];
}

__global__ void k_scan3() {
    int b = blockIdx.x, t = threadIdx.x;
    int add = b ? g_bsum[b - 1] : 0;
    int base = b * 1024 + t * 4;
    #pragma unroll
    for (int i = 0; i < 4; ++i) {
        int idx = base + i;
        if (idx <= N_NODESC) {
            int r = g_rowptr[idx] + add;
            g_rowptr[idx] = r;
            if (idx < N_NODESC) g_fill[idx] = r;
        }
    }
}

__global__ void k_scatter(const int* __restrict__ ei) {
    bool is64 = (g_nz_ei == 0u);
    int e = blockIdx.x * blockDim.x + threadIdx.x;
    if (e < N_EDGESC) {
        int s = idx_at(ei, e, is64);
        int d = idx_at(ei, (long long)N_EDGESC + e, is64);
        int pos = atomicAdd(&g_fill[s], 1);
        g_csr[pos] = d;
    }
}

// one warp per hash row: coalesced scan + ballot pick
__global__ void k_hash(const float* __restrict__ Hm, int l) {
    int warp = (blockIdx.x * blockDim.x + threadIdx.x) >> 5;
    int lane = threadIdx.x & 31;
    if (warp >= 4 * DIM) return;
    const float* row = Hm + (size_t)warp * 128;
    int col = 0; float sgn = 0.f;
    #pragma unroll
    for (int i = 0; i < 4; ++i) {
        float v = row[lane + i * 32];
        if (v != 0.f) { col = lane + i * 32; sgn = v; }
    }
    unsigned m = __ballot_sync(0xffffffffu, sgn != 0.f);
    if (m) {
        int src = __ffs(m) - 1;
        col = __shfl_sync(0xffffffffu, col, src);
        sgn = __shfl_sync(0xffffffffu, sgn, src);
    }
    if (lane == 0) { g_hcol[l][warp] = col; g_hsign[l][warp] = sgn; }
}

// g_Wh[l][n=j][k=r] = fp16( cat(Ws, Wp_eff)[r][j] )
__global__ void k_buildW(const float* __restrict__ Wp, const float* __restrict__ Ws, int l) {
    int idx = blockIdx.x * blockDim.x + threadIdx.x;
    if (idx >= KTOT * DIM) return;
    int r = idx >> 9;        // k
    int j = idx & 511;       // n
    float w;
    if (r < 512) {
        w = Ws[r * DIM + j];
    } else {
        int d = r - 512;
        w = 0.f;
        #pragma unroll
        for (int k = 0; k < 4; ++k) {
            int c = g_hcol[l][k * DIM + d];
            w += g_hsign[l][k * DIM + d] * Wp[(size_t)(k * 128 + c) * DIM + j];
        }
    }
    __half h = __float2half_rn(w);
    g_Wh[l][(size_t)j * KTOT + r] = *reinterpret_cast<u16*>(&h);
}

// x -> fp16 plane
__global__ void k_copy_x(const float* __restrict__ x) {
    int i = blockIdx.x * blockDim.x + threadIdx.x;   // float4 index
    if (i >= N_NODESC * (DIM / 4)) return;
    size_t off = (size_t)i * 4;
    float4 v = *(const float4*)(x + off);
    uint2 p;
    p.x = pack2h(v.x, v.y);
    p.y = pack2h(v.z, v.w);
    *(uint2*)(g_xh + off) = p;
}

// ---------------- aggregation: gather-mean over fp16 plane -------------------
__global__ void __launch_bounds__(256)
k_agg(const u16* __restrict__ h, u16* __restrict__ agg) {
    int n = blockIdx.x * 4 + (threadIdx.x >> 6);
    if (n >= N_NODESC) return;
    int t = threadIdx.x & 63;
    int s = g_rowptr[n], e = g_rowptr[n + 1];
    size_t off = (size_t)n * DIM + t * 8;
    uint4 o;
    if (e == s) {
        o = *(const uint4*)(h + off);
    } else {
        float a[8] = {0.f, 0.f, 0.f, 0.f, 0.f, 0.f, 0.f, 0.f};
        int j = s;
        for (; j + 2 <= e; j += 2) {
            int d0 = g_csr[j], d1 = g_csr[j + 1];
            uint4 v0 = *(const uint4*)(h + (size_t)d0 * DIM + t * 8);
            uint4 v1 = *(const uint4*)(h + (size_t)d1 * DIM + t * 8);
            acc8(a, v0);
            acc8(a, v1);
        }
        if (j < e) {
            uint4 v = *(const uint4*)(h + (size_t)g_csr[j] * DIM + t * 8);
            acc8(a, v);
        }
        float inv = 1.f / (float)(e - s);
        o.x = pack2h(a[0] * inv, a[1] * inv);
        o.y = pack2h(a[2] * inv, a[3] * inv);
        o.z = pack2h(a[4] * inv, a[5] * inv);
        o.w = pack2h(a[6] * inv, a[7] * inv);
    }
    *(uint4*)(agg + off) = o;
}

// ---------------- fp16 GEMM: out = elu([h|agg] @ W + b) ----------------------
// BM=128, BN=128, BK=32 halves, 4-stage cp.async ring, one sync per slab.
#define AWB      80                      // bytes per smem row
#define PLANEB   (128 * AWB)             // 10240 bytes
#define STAGEB   (2 * PLANEB)            // 20480 bytes
#define NSTAGE   4
#define GEMM_SMEM (NSTAGE * STAGEB)      // 81920 bytes

__global__ void __launch_bounds__(256, 2)
k_gemmh(const u16* __restrict__ Hh, const u16* __restrict__ Gh,
        const u16* __restrict__ W, const float* __restrict__ bias,
        u16* __restrict__ C16)
{
    extern __shared__ char S[];
    const u32 sb   = smem_u32(S);
    const int tid  = threadIdx.x;
    const int lane = tid & 31;
    const int wid  = tid >> 5;
    const int g    = lane >> 2;
    const int t4   = lane & 3;
    const int wm   = (wid & 1) * 64;
    const int wn   = (wid >> 1) * 32;
    const int m0   = blockIdx.y * 128;
    const int n0   = blockIdx.x * 128;

    float acc[4][4][4];
    #pragma unroll
    for (int i = 0; i < 4; ++i)
        #pragma unroll
        for (int j = 0; j < 4; ++j)
            #pragma unroll
            for (int k = 0; k < 4; ++k) acc[i][j][k] = 0.f;

    const int qr = tid >> 2;     // 0..63
    const int qc = tid & 3;      // 16B chunk within row

    auto load_stage = [&](int kt) {
        const int st = kt & (NSTAGE - 1);
        const int kk = kt * 32;
        const u16* Asrc = (kk & 512) ? Gh : Hh;
        const int kc = kk & 511;
        const u32 ab = sb + st * STAGEB;
        #pragma unroll
        for (int i = 0; i < 2; ++i) {
            int row = qr + i * 64;
            int grow = m0 + row;
            int ok = (grow < N_NODESC) ? 16 : 0;
            const u16* src = Asrc + (size_t)(grow < N_NODESC ? grow : 0) * DIM + kc + qc * 8;
            cp16z(ab + row * AWB + qc * 16, src, ok);
        }
        const u32 bb = sb + st * STAGEB + PLANEB;
        #pragma unroll
        for (int i = 0; i < 2; ++i) {
            int row = qr + i * 64;
            const u16* src = W + (size_t)(n0 + row) * KTOT + kk + qc * 8;
            cp16(bb + row * AWB + qc * 16, src);
        }
        asm volatile("cp.async.commit_group;\n");
    };

    load_stage(0);
    load_stage(1);
    load_stage(2);

    const u32 a_row  = wm + (lane & 15);
    const u32 a_koff = (lane >> 4) << 4;
    const u32 b_row  = wn + ((lane >> 4) << 3) + (lane & 7);
    const u32 b_koff = ((lane >> 3) & 1) << 4;

    const int KT = KTOT / 32;   // 32
    for (int kt = 0; kt < KT; ++kt) {
        const int st = kt & (NSTAGE - 1);
        asm volatile("cp.async.wait_group 2;\n");
        __syncthreads();
        // issue next load BEFORE compute (distinct ring slot; prev reader synced)
        if (kt + 3 < KT) load_stage(kt + 3);
        else asm volatile("cp.async.commit_group;\n");   // keep group count valid
        const u32 ab = sb + st * STAGEB;
        const u32 bb = ab + PLANEB;
        #pragma unroll
        for (int ks2 = 0; ks2 < 2; ++ks2) {
            const u32 ko = ks2 << 5;
            u32 a[4][4], b[4][2];
            #pragma unroll
            for (int mi = 0; mi < 4; ++mi)
                ldm_x4(a[mi][0], a[mi][1], a[mi][2], a[mi][3],
                       ab + (a_row + mi * 16) * AWB + a_koff + ko);
            #pragma unroll
            for (int nip = 0; nip < 2; ++nip)
                ldm_x4(b[nip * 2][0], b[nip * 2][1], b[nip * 2 + 1][0], b[nip * 2 + 1][1],
                       bb + (b_row + nip * 16) * AWB + b_koff + ko);
            #pragma unroll
            for (int mi = 0; mi < 4; ++mi)
                #pragma unroll
                for (int ni = 0; ni < 4; ++ni)
                    mma_f16(acc[mi][ni], a[mi], b[ni]);
        }
    }

    // epilogue: bias + elu -> fp16 plane
    #pragma unroll
    for (int mi = 0; mi < 4; ++mi) {
        int rr0 = m0 + wm + mi * 16 + g;
        #pragma unroll
        for (int ni = 0; ni < 4; ++ni) {
            int col = n0 + wn + ni * 8 + 2 * t4;
            float bb0 = bias[col], bb1 = bias[col + 1];
            #pragma unroll
            for (int half = 0; half < 2; ++half) {
                int row = rr0 + half * 8;
                if (row < N_NODESC) {
                    float vx = eluf(acc[mi][ni][half * 2 + 0] + bb0);
                    float vy = eluf(acc[mi][ni][half * 2 + 1] + bb1);
                    *(u32*)(C16 + (size_t)row * DIM + col) = pack2h(vx, vy);
                }
            }
        }
    }
}

// ---------------- pooling + classifier --------------------------------------
__global__ void k_pool(const u16* __restrict__ h, const int* __restrict__ batch) {
    bool is64 = (g_nz_batch == 0u);
    int d  = blockIdx.y * 128 + threadIdx.x;
    int n0 = blockIdx.x * 128;
    int ne = min(n0 + 128, N_NODESC);
    int cur = idx_at(batch, n0, is64);
    float acc = 0.f;
    for (int n = n0; n < ne; ++n) {
        int b = idx_at(batch, n, is64);
        if (b != cur) { atomicAdd(&g_gsum[cur * DIM + d], acc); acc = 0.f; cur = b; }
        acc += __half2float(*reinterpret_cast<const __half*>(h + (size_t)n * DIM + d));
    }
    atomicAdd(&g_gsum[cur * DIM + d], acc);
}

__global__ void k_cnt(const int* __restrict__ batch) {
    __shared__ int hist[NUM_GRAPHS];
    int t = threadIdx.x;
    if (t < NUM_GRAPHS) hist[t] = 0;
    __syncthreads();
    bool is64 = (g_nz_batch == 0u);
    int n = blockIdx.x * blockDim.x + t;
    if (n < N_NODESC) atomicAdd(&hist[idx_at(batch, n, is64)], 1);
    __syncthreads();
    if (t < NUM_GRAPHS && hist[t]) atomicAdd(&g_gcnt[t], (float)hist[t]);
}

__global__ void k_cls(const float* __restrict__ Wc, const float* __restrict__ bc,
                      float* __restrict__ out) {
    int gid = blockIdx.x;
    int t = threadIdx.x;
    __shared__ float gv[DIM];
    __shared__ float red[NUM_CLASSES][128];
    float inv = 1.f / fmaxf(g_gcnt[gid], 1.f);
    for (int d = t; d < DIM; d += 128) gv[d] = g_gsum[gid * DIM + d] * inv;
    __syncthreads();
    float p[NUM_CLASSES];
    #pragma unroll
    for (int c = 0; c < NUM_CLASSES; ++c) p[c] = 0.f;
    for (int d = t; d < DIM; d += 128) {
        float v = gv[d];
        #pragma unroll
        for (int c = 0; c < NUM_CLASSES; ++c) p[c] += v * Wc[d * NUM_CLASSES + c];
    }
    #pragma unroll
    for (int c = 0; c < NUM_CLASSES; ++c) red[c][t] = p[c];
    __syncthreads();
    for (int off = 64; off > 0; off >>= 1) {
        if (t < off)
            #pragma unroll
            for (int c = 0; c < NUM_CLASSES; ++c) red[c][t] += red[c][t + off];
        __syncthreads();
    }
    if (t < NUM_CLASSES) out[gid * NUM_CLASSES + t] = red[t][0] + bc[t];
}

// ---------------- launch -----------------------------------------------------
extern "C" void kernel_launch(void* const* d_in, const int* in_sizes, int n_in,
                              void* d_out, int out_size) {
    const float* x     = (const float*)d_in[0];
    const int*   ei    = (const int*)d_in[1];
    const int*   batch = (const int*)d_in[2];
    const float* Hm1   = (const float*)d_in[3];
    const float* Wp1   = (const float*)d_in[4];
    const float* Ws1   = (const float*)d_in[5];
    const float* b1    = (const float*)d_in[6];
    const float* Hm2   = (const float*)d_in[7];
    const float* Wp2   = (const float*)d_in[8];
    const float* Ws2   = (const float*)d_in[9];
    const float* b2    = (const float*)d_in[10];
    const float* Wc    = (const float*)d_in[11];
    const float* bc    = (const float*)d_in[12];
    float*       out   = (float*)d_out;

    u16 *xh, *agh, *h1h, *h2h, *wh;
    cudaGetSymbolAddress((void**)&xh,  g_xh);
    cudaGetSymbolAddress((void**)&agh, g_agh);
    cudaGetSymbolAddress((void**)&h1h, g_h1h);
    cudaGetSymbolAddress((void**)&h2h, g_h2h);
    cudaGetSymbolAddress((void**)&wh,  g_Wh);
    u16* W0 = wh;
    u16* W1 = wh + (size_t)DIM * KTOT;

    cudaFuncSetAttribute(k_gemmh, cudaFuncAttributeMaxDynamicSharedMemorySize, GEMM_SMEM);

    // dtype detection (flags statically zero-initialized; OR is idempotent across replays)
    k_detect<<<256, 256>>>((const unsigned*)ei, N_EDGESC, 0);
    k_detect<<<64, 256>>>((const unsigned*)batch, N_NODESC / 2, 1);

    // setup
    k_zero_meta<<<196, 256>>>();
    k_count<<<(N_EDGESC + 255) / 256, 256>>>(ei);
    k_scan1<<<SCAN_NB, 256>>>();
    k_scan2<<<1, 64>>>();
    k_scan3<<<SCAN_NB, 256>>>();
    k_scatter<<<(N_EDGESC + 255) / 256, 256>>>(ei);
    k_hash<<<(4 * DIM * 32 + 255) / 256, 256>>>(Hm1, 0);
    k_hash<<<(4 * DIM * 32 + 255) / 256, 256>>>(Hm2, 1);
    k_buildW<<<(KTOT * DIM + 255) / 256, 256>>>(Wp1, Ws1, 0);
    k_buildW<<<(KTOT * DIM + 255) / 256, 256>>>(Wp2, Ws2, 1);
    k_copy_x<<<(N_NODESC * (DIM / 4) + 255) / 256, 256>>>(x);

    dim3 ggrid(DIM / 128, (N_NODESC + 127) / 128);   // (4, 391)
    int aggrid = (N_NODESC + 3) / 4;                 // 12500

    // layer 1
    k_agg<<<aggrid, 256>>>(xh, agh);
    k_gemmh<<<ggrid, 256, GEMM_SMEM>>>(xh, agh, W0, b1, h1h);

    // layer 2
    k_agg<<<aggrid, 256>>>(h1h, agh);
    k_gemmh<<<ggrid, 256, GEMM_SMEM>>>(h1h, agh, W1, b2, h2h);

    // pool + classify
    k_pool<<<dim3((N_NODESC + 127) / 128, 4), 128>>>(h2h, batch);
    k_cnt<<<196, 256>>>(batch);
    k_cls<<<NUM_GRAPHS, 128>>>(Wc, bc, out);
}

// round 11
// speedup vs baseline: 2.2890x; 1.0007x over previous
#include <cuda_runtime.h>
#include <cuda_fp16.h>
#include <cstdint>
#include <math.h>

#define N_NODESC   50000
#define N_EDGESC   800000
#define DIM        512
#define KTOT       1024
#define NUM_GRAPHS 64
#define NUM_CLASSES 10
#define SCAN_NB    ((N_NODESC + 1 + 1023) / 1024)   // 49

typedef unsigned short u16;
typedef unsigned int   u32;

// ---------------- scratch (device globals; no allocation allowed) ----------
__device__ __align__(16) u16   g_xh [(size_t)N_NODESC * DIM];   // x, fp16
__device__ __align__(16) u16   g_agh[(size_t)N_NODESC * DIM];   // agg, fp16
__device__ __align__(16) u16   g_h1h[(size_t)N_NODESC * DIM];   // h1, fp16
__device__ __align__(16) u16   g_h2h[(size_t)N_NODESC * DIM];   // h2, fp16
__device__ __align__(16) u16   g_Wh [2][(size_t)DIM * KTOT];    // [layer][n][k], fp16
__device__ int   g_rowptr[N_NODESC + 1];
__device__ int   g_fill  [N_NODESC];
__device__ int   g_csr   [N_EDGESC];
__device__ int   g_hcol [2][4 * DIM];
__device__ float g_hsign[2][4 * DIM];
__device__ float g_gsum[NUM_GRAPHS * DIM];
__device__ float g_gcnt[NUM_GRAPHS];
__device__ int   g_bsum[64];
__device__ unsigned g_nz_ei = 0;      // static zero init; detect only ORs (idempotent)
__device__ unsigned g_nz_batch = 0;

// ---------------- helpers ---------------------------------------------------
__device__ __forceinline__ float eluf(float x) { return x > 0.f ? x : expm1f(x); }

__device__ __forceinline__ int idx_at(const int* p, long long i, bool is64) {
    return is64 ? p[2 * i] : p[i];
}

__device__ __forceinline__ void mma_f16(float* d, const u32* a, const u32* b) {
    asm volatile(
        "mma.sync.aligned.m16n8k16.row.col.f32.f16.f16.f32 "
        "{%0,%1,%2,%3},{%4,%5,%6,%7},{%8,%9},{%0,%1,%2,%3};\n"
        : "+f"(d[0]), "+f"(d[1]), "+f"(d[2]), "+f"(d[3])
        : "r"(a[0]), "r"(a[1]), "r"(a[2]), "r"(a[3]), "r"(b[0]), "r"(b[1]));
}
__device__ __forceinline__ void ldm_x4(u32& r0, u32& r1, u32& r2, u32& r3, u32 addr) {
    asm volatile("ldmatrix.sync.aligned.m8n8.x4.shared.b16 {%0,%1,%2,%3}, [%4];"
                 : "=r"(r0), "=r"(r1), "=r"(r2), "=r"(r3) : "r"(addr));
}
__device__ __forceinline__ void cp16(u32 dst, const void* src) {
    asm volatile("cp.async.cg.shared.global [%0], [%1], 16;\n" :: "r"(dst), "l"(src));
}
__device__ __forceinline__ void cp16z(u32 dst, const void* src, int nbytes) {
    asm volatile("cp.async.cg.shared.global [%0], [%1], 16, %2;\n"
                 :: "r"(dst), "l"(src), "r"(nbytes));
}
__device__ __forceinline__ u32 smem_u32(const void* p) {
    u32 a;
    asm("{ .reg .u64 t; cvta.to.shared.u64 t, %1; cvt.u32.u64 %0, t; }" : "=r"(a) : "l"(p));
    return a;
}
__device__ __forceinline__ u32 pack2h(float a, float b) {
    __half2 h = __floats2half2_rn(a, b);
    return *reinterpret_cast<u32*>(&h);
}
__device__ __forceinline__ void acc8(float* a, uint4 v) {
    float2 f0 = __half22float2(*reinterpret_cast<__half2*>(&v.x));
    float2 f1 = __half22float2(*reinterpret_cast<__half2*>(&v.y));
    float2 f2 = __half22float2(*reinterpret_cast<__half2*>(&v.z));
    float2 f3 = __half22float2(*reinterpret_cast<__half2*>(&v.w));
    a[0] += f0.x; a[1] += f0.y; a[2] += f1.x; a[3] += f1.y;
    a[4] += f2.x; a[5] += f2.y; a[6] += f3.x; a[7] += f3.y;
}

// ---------------- dtype detection ------------------------------------------
__global__ void k_detect(const unsigned* __restrict__ p, long long n, int which) {
    unsigned acc = 0;
    for (long long i = blockIdx.x * blockDim.x + threadIdx.x; i < n;
         i += (long long)gridDim.x * blockDim.x)
        acc |= p[2 * i + 1];
    acc |= __shfl_xor_sync(0xffffffffu, acc, 16);
    acc |= __shfl_xor_sync(0xffffffffu, acc, 8);
    acc |= __shfl_xor_sync(0xffffffffu, acc, 4);
    acc |= __shfl_xor_sync(0xffffffffu, acc, 2);
    acc |= __shfl_xor_sync(0xffffffffu, acc, 1);
    if ((threadIdx.x & 31) == 0 && acc) {
        if (which == 0) atomicOr(&g_nz_ei, acc);
        else            atomicOr(&g_nz_batch, acc);
    }
}

// ---------------- setup kernels --------------------------------------------
__global__ void k_zero_meta() {
    int i = blockIdx.x * blockDim.x + threadIdx.x;
    if (i <= N_NODESC) g_rowptr[i] = 0;
    if (i < NUM_GRAPHS * DIM) g_gsum[i] = 0.f;
    if (i < NUM_GRAPHS) g_gcnt[i] = 0.f;
}

__global__ void k_count(const int* __restrict__ ei) {
    bool is64 = (g_nz_ei == 0u);
    int e = blockIdx.x * blockDim.x + threadIdx.x;
    if (e < N_EDGESC) {
        int s = idx_at(ei, e, is64);
        atomicAdd(&g_rowptr[s + 1], 1);
    }
}

__global__ void k_scan1() {
    __shared__ int wsum[8];
    int b = blockIdx.x, t = threadIdx.x;
    int base = b * 1024 + t * 4;
    int v0, v1, v2, v3;
    v0 = (base + 0 <= N_NODESC) ? g_rowptr[base + 0] : 0;
    v1 = (base + 1 <= N_NODESC) ? g_rowptr[base + 1] : 0;
    v2 = (base + 2 <= N_NODESC) ? g_rowptr[base + 2] : 0;
    v3 = (base + 3 <= N_NODESC) ? g_rowptr[base + 3] : 0;
    v1 += v0; v2 += v1; v3 += v2;
    int lane = t & 31, w = t >> 5;
    int s = v3;
    #pragma unroll
    for (int o = 1; o < 32; o <<= 1) {
        int n = __shfl_up_sync(0xffffffffu, s, o);
        if (lane >= o) s += n;
    }
    if (lane == 31) wsum[w] = s;
    __syncthreads();
    if (t < 8) {
        int x = wsum[t];
        #pragma unroll
        for (int o = 1; o < 8; o <<= 1) {
            int n = __shfl_up_sync(0x000000ffu, x, o);
            if (t >= o) x += n;
        }
        wsum[t] = x;
    }
    __syncthreads();
    int excl = (w ? wsum[w - 1] : 0) + (s - v3);
    v0 += excl; v1 += excl; v2 += excl; v3 += excl;
    if (base + 0 <= N_NODESC) g_rowptr[base + 0] = v0;
    if (base + 1 <= N_NODESC) g_rowptr[base + 1] = v1;
    if (base + 2 <= N_NODESC) g_rowptr[base + 2] = v2;
    if (base + 3 <= N_NODESC) g_rowptr[base + 3] = v3;
    if (t == 0) g_bsum[b] = wsum[7];
}

__global__ void k_scan2() {
    __shared__ int sh[64];
    int t = threadIdx.x;
    sh[t] = (t < SCAN_NB) ? g_bsum[t] : 0;
    __syncthreads();
    for (int o = 1; o < 64; o <<= 1) {
        int a = (t >= o) ? sh[t - o] : 0;
        __syncthreads();
        sh[t] += a;
        __syncthreads();
    }
    g_bsum[t] = sh[t];
}

__global__ void k_scan3() {
    int b = blockIdx.x, t = threadIdx.x;
    int add = b ? g_bsum[b - 1] : 0;
    int base = b * 1024 + t * 4;
    #pragma unroll
    for (int i = 0; i < 4; ++i) {
        int idx = base + i;
        if (idx <= N_NODESC) {
            int r = g_rowptr[idx] + add;
            g_rowptr[idx] = r;
            if (idx < N_NODESC) g_fill[idx] = r;
        }
    }
}

__global__ void k_scatter(const int* __restrict__ ei) {
    bool is64 = (g_nz_ei == 0u);
    int e = blockIdx.x * blockDim.x + threadIdx.x;
    if (e < N_EDGESC) {
        int s = idx_at(ei, e, is64);
        int d = idx_at(ei, (long long)N_EDGESC + e, is64);
        int pos = atomicAdd(&g_fill[s], 1);
        g_csr[pos] = d;
    }
}

// one warp per hash row: coalesced scan + ballot pick
__global__ void k_hash(const float* __restrict__ Hm, int l) {
    int warp = (blockIdx.x * blockDim.x + threadIdx.x) >> 5;
    int lane = threadIdx.x & 31;
    if (warp >= 4 * DIM) return;
    const float* row = Hm + (size_t)warp * 128;
    int col = 0; float sgn = 0.f;
    #pragma unroll
    for (int i = 0; i < 4; ++i) {
        float v = row[lane + i * 32];
        if (v != 0.f) { col = lane + i * 32; sgn = v; }
    }
    unsigned m = __ballot_sync(0xffffffffu, sgn != 0.f);
    if (m) {
        int src = __ffs(m) - 1;
        col = __shfl_sync(0xffffffffu, col, src);
        sgn = __shfl_sync(0xffffffffu, sgn, src);
    }
    if (lane == 0) { g_hcol[l][warp] = col; g_hsign[l][warp] = sgn; }
}

// g_Wh[l][n=j][k=r] = fp16( cat(Ws, Wp_eff)[r][j] )
__global__ void k_buildW(const float* __restrict__ Wp, const float* __restrict__ Ws, int l) {
    int idx = blockIdx.x * blockDim.x + threadIdx.x;
    if (idx >= KTOT * DIM) return;
    int r = idx >> 9;        // k
    int j = idx & 511;       // n
    float w;
    if (r < 512) {
        w = Ws[r * DIM + j];
    } else {
        int d = r - 512;
        w = 0.f;
        #pragma unroll
        for (int k = 0; k < 4; ++k) {
            int c = g_hcol[l][k * DIM + d];
            w += g_hsign[l][k * DIM + d] * Wp[(size_t)(k * 128 + c) * DIM + j];
        }
    }
    __half h = __float2half_rn(w);
    g_Wh[l][(size_t)j * KTOT + r] = *reinterpret_cast<u16*>(&h);
}

// x -> fp16 plane
__global__ void k_copy_x(const float* __restrict__ x) {
    int i = blockIdx.x * blockDim.x + threadIdx.x;   // float4 index
    if (i >= N_NODESC * (DIM / 4)) return;
    size_t off = (size_t)i * 4;
    float4 v = *(const float4*)(x + off);
    uint2 p;
    p.x = pack2h(v.x, v.y);
    p.y = pack2h(v.z, v.w);
    *(uint2*)(g_xh + off) = p;
}

// ---------------- aggregation: gather-mean over fp16 plane -------------------
__global__ void __launch_bounds__(256)
k_agg(const u16* __restrict__ h, u16* __restrict__ agg) {
    int n = blockIdx.x * 4 + (threadIdx.x >> 6);
    if (n >= N_NODESC) return;
    int t = threadIdx.x & 63;
    int s = g_rowptr[n], e = g_rowptr[n + 1];
    size_t off = (size_t)n * DIM + t * 8;
    uint4 o;
    if (e == s) {
        o = *(const uint4*)(h + off);
    } else {
        float a[8] = {0.f, 0.f, 0.f, 0.f, 0.f, 0.f, 0.f, 0.f};
        int j = s;
        for (; j + 2 <= e; j += 2) {
            int d0 = g_csr[j], d1 = g_csr[j + 1];
            uint4 v0 = *(const uint4*)(h + (size_t)d0 * DIM + t * 8);
            uint4 v1 = *(const uint4*)(h + (size_t)d1 * DIM + t * 8);
            acc8(a, v0);
            acc8(a, v1);
        }
        if (j < e) {
            uint4 v = *(const uint4*)(h + (size_t)g_csr[j] * DIM + t * 8);
            acc8(a, v);
        }
        float inv = 1.f / (float)(e - s);
        o.x = pack2h(a[0] * inv, a[1] * inv);
        o.y = pack2h(a[2] * inv, a[3] * inv);
        o.z = pack2h(a[4] * inv, a[5] * inv);
        o.w = pack2h(a[6] * inv, a[7] * inv);
    }
    *(uint4*)(agg + off) = o;
}

// ---------------- fp16 GEMM: out = elu([h|agg] @ W + b) ----------------------
// BM=128, BN=128, BK=32 halves, 4-stage cp.async ring, one sync per slab.
#define AWB      80                      // bytes per smem row
#define PLANEB   (128 * AWB)             // 10240 bytes
#define STAGEB   (2 * PLANEB)            // 20480 bytes
#define NSTAGE   4
#define GEMM_SMEM (NSTAGE * STAGEB)      // 81920 bytes

__global__ void __launch_bounds__(256, 2)
k_gemmh(const u16* __restrict__ Hh, const u16* __restrict__ Gh,
        const u16* __restrict__ W, const float* __restrict__ bias,
        u16* __restrict__ C16)
{
    extern __shared__ char S[];
    const u32 sb   = smem_u32(S);
    const int tid  = threadIdx.x;
    const int lane = tid & 31;
    const int wid  = tid >> 5;
    const int g    = lane >> 2;
    const int t4   = lane & 3;
    const int wm   = (wid & 1) * 64;
    const int wn   = (wid >> 1) * 32;
    const int m0   = blockIdx.y * 128;
    const int n0   = blockIdx.x * 128;

    float acc[4][4][4];
    #pragma unroll
    for (int i = 0; i < 4; ++i)
        #pragma unroll
        for (int j = 0; j < 4; ++j)
            #pragma unroll
            for (int k = 0; k < 4; ++k) acc[i][j][k] = 0.f;

    const int qr = tid >> 2;     // 0..63
    const int qc = tid & 3;      // 16B chunk within row

    auto load_stage = [&](int kt) {
        const int st = kt & (NSTAGE - 1);
        const int kk = kt * 32;
        const u16* Asrc = (kk & 512) ? Gh : Hh;
        const int kc = kk & 511;
        const u32 ab = sb + st * STAGEB;
        #pragma unroll
        for (int i = 0; i < 2; ++i) {
            int row = qr + i * 64;
            int grow = m0 + row;
            int ok = (grow < N_NODESC) ? 16 : 0;
            const u16* src = Asrc + (size_t)(grow < N_NODESC ? grow : 0) * DIM + kc + qc * 8;
            cp16z(ab + row * AWB + qc * 16, src, ok);
        }
        const u32 bb = sb + st * STAGEB + PLANEB;
        #pragma unroll
        for (int i = 0; i < 2; ++i) {
            int row = qr + i * 64;
            const u16* src = W + (size_t)(n0 + row) * KTOT + kk + qc * 8;
            cp16(bb + row * AWB + qc * 16, src);
        }
        asm volatile("cp.async.commit_group;\n");
    };

    load_stage(0);
    load_stage(1);
    load_stage(2);

    const u32 a_row  = wm + (lane & 15);
    const u32 a_koff = (lane >> 4) << 4;
    const u32 b_row  = wn + ((lane >> 4) << 3) + (lane & 7);
    const u32 b_koff = ((lane >> 3) & 1) << 4;

    const int KT = KTOT / 32;   // 32
    for (int kt = 0; kt < KT; ++kt) {
        const int st = kt & (NSTAGE - 1);
        asm volatile("cp.async.wait_group 2;\n");
        __syncthreads();
        // issue next load BEFORE compute (distinct ring slot; prev reader synced)
        if (kt + 3 < KT) load_stage(kt + 3);
        else asm volatile("cp.async.commit_group;\n");   // keep group count valid
        const u32 ab = sb + st * STAGEB;
        const u32 bb = ab + PLANEB;
        #pragma unroll
        for (int ks2 = 0; ks2 < 2; ++ks2) {
            const u32 ko = ks2 << 5;
            u32 a[4][4], b[4][2];
            #pragma unroll
            for (int mi = 0; mi < 4; ++mi)
                ldm_x4(a[mi][0], a[mi][1], a[mi][2], a[mi][3],
                       ab + (a_row + mi * 16) * AWB + a_koff + ko);
            #pragma unroll
            for (int nip = 0; nip < 2; ++nip)
                ldm_x4(b[nip * 2][0], b[nip * 2][1], b[nip * 2 + 1][0], b[nip * 2 + 1][1],
                       bb + (b_row + nip * 16) * AWB + b_koff + ko);
            #pragma unroll
            for (int mi = 0; mi < 4; ++mi)
                #pragma unroll
                for (int ni = 0; ni < 4; ++ni)
                    mma_f16(acc[mi][ni], a[mi], b[ni]);
        }
    }

    // epilogue: bias + elu -> fp16 plane
    #pragma unroll
    for (int mi = 0; mi < 4; ++mi) {
        int rr0 = m0 + wm + mi * 16 + g;
        #pragma unroll
        for (int ni = 0; ni < 4; ++ni) {
            int col = n0 + wn + ni * 8 + 2 * t4;
            float bb0 = bias[col], bb1 = bias[col + 1];
            #pragma unroll
            for (int half = 0; half < 2; ++half) {
                int row = rr0 + half * 8;
                if (row < N_NODESC) {
                    float vx = eluf(acc[mi][ni][half * 2 + 0] + bb0);
                    float vy = eluf(acc[mi][ni][half * 2 + 1] + bb1);
                    *(u32*)(C16 + (size_t)row * DIM + col) = pack2h(vx, vy);
                }
            }
        }
    }
}

// ---------------- pooling + classifier --------------------------------------
__global__ void k_pool(const u16* __restrict__ h, const int* __restrict__ batch) {
    bool is64 = (g_nz_batch == 0u);
    int d  = blockIdx.y * 128 + threadIdx.x;
    int n0 = blockIdx.x * 128;
    int ne = min(n0 + 128, N_NODESC);
    int cur = idx_at(batch, n0, is64);
    float acc = 0.f;
    for (int n = n0; n < ne; ++n) {
        int b = idx_at(batch, n, is64);
        if (b != cur) { atomicAdd(&g_gsum[cur * DIM + d], acc); acc = 0.f; cur = b; }
        acc += __half2float(*reinterpret_cast<const __half*>(h + (size_t)n * DIM + d));
    }
    atomicAdd(&g_gsum[cur * DIM + d], acc);
}

__global__ void k_cnt(const int* __restrict__ batch) {
    __shared__ int hist[NUM_GRAPHS];
    int t = threadIdx.x;
    if (t < NUM_GRAPHS) hist[t] = 0;
    __syncthreads();
    bool is64 = (g_nz_batch == 0u);
    int n = blockIdx.x * blockDim.x + t;
    if (n < N_NODESC) atomicAdd(&hist[idx_at(batch, n, is64)], 1);
    __syncthreads();
    if (t < NUM_GRAPHS && hist[t]) atomicAdd(&g_gcnt[t], (float)hist[t]);
}

__global__ void k_cls(const float* __restrict__ Wc, const float* __restrict__ bc,
                      float* __restrict__ out) {
    int gid = blockIdx.x;
    int t = threadIdx.x;
    __shared__ float gv[DIM];
    __shared__ float red[NUM_CLASSES][128];
    float inv = 1.f / fmaxf(g_gcnt[gid], 1.f);
    for (int d = t; d < DIM; d += 128) gv[d] = g_gsum[gid * DIM + d] * inv;
    __syncthreads();
    float p[NUM_CLASSES];
    #pragma unroll
    for (int c = 0; c < NUM_CLASSES; ++c) p[c] = 0.f;
    for (int d = t; d < DIM; d += 128) {
        float v = gv[d];
        #pragma unroll
        for (int c = 0; c < NUM_CLASSES; ++c) p[c] += v * Wc[d * NUM_CLASSES + c];
    }
    #pragma unroll
    for (int c = 0; c < NUM_CLASSES; ++c) red[c][t] = p[c];
    __syncthreads();
    for (int off = 64; off > 0; off >>= 1) {
        if (t < off)
            #pragma unroll
            for (int c = 0; c < NUM_CLASSES; ++c) red[c][t] += red[c][t + off];
        __syncthreads();
    }
    if (t < NUM_CLASSES) out[gid * NUM_CLASSES + t] = red[t][0] + bc[t];
}

// ---------------- launch -----------------------------------------------------
extern "C" void kernel_launch(void* const* d_in, const int* in_sizes, int n_in,
                              void* d_out, int out_size) {
    const float* x     = (const float*)d_in[0];
    const int*   ei    = (const int*)d_in[1];
    const int*   batch = (const int*)d_in[2];
    const float* Hm1   = (const float*)d_in[3];
    const float* Wp1   = (const float*)d_in[4];
    const float* Ws1   = (const float*)d_in[5];
    const float* b1    = (const float*)d_in[6];
    const float* Hm2   = (const float*)d_in[7];
    const float* Wp2   = (const float*)d_in[8];
    const float* Ws2   = (const float*)d_in[9];
    const float* b2    = (const float*)d_in[10];
    const float* Wc    = (const float*)d_in[11];
    const float* bc    = (const float*)d_in[12];
    float*       out   = (float*)d_out;

    u16 *xh, *agh, *h1h, *h2h, *wh;
    cudaGetSymbolAddress((void**)&xh,  g_xh);
    cudaGetSymbolAddress((void**)&agh, g_agh);
    cudaGetSymbolAddress((void**)&h1h, g_h1h);
    cudaGetSymbolAddress((void**)&h2h, g_h2h);
    cudaGetSymbolAddress((void**)&wh,  g_Wh);
    u16* W0 = wh;
    u16* W1 = wh + (size_t)DIM * KTOT;

    cudaFuncSetAttribute(k_gemmh, cudaFuncAttributeMaxDynamicSharedMemorySize, GEMM_SMEM);

    // dtype detection (flags statically zero-initialized; OR is idempotent across replays)
    k_detect<<<256, 256>>>((const unsigned*)ei, N_EDGESC, 0);
    k_detect<<<64, 256>>>((const unsigned*)batch, N_NODESC / 2, 1);

    // setup
    k_zero_meta<<<196, 256>>>();
    k_count<<<(N_EDGESC + 255) / 256, 256>>>(ei);
    k_scan1<<<SCAN_NB, 256>>>();
    k_scan2<<<1, 64>>>();
    k_scan3<<<SCAN_NB, 256>>>();
    k_scatter<<<(N_EDGESC + 255) / 256, 256>>>(ei);
    k_hash<<<(4 * DIM * 32 + 255) / 256, 256>>>(Hm1, 0);
    k_hash<<<(4 * DIM * 32 + 255) / 256, 256>>>(Hm2, 1);
    k_buildW<<<(KTOT * DIM + 255) / 256, 256>>>(Wp1, Ws1, 0);
    k_buildW<<<(KTOT * DIM + 255) / 256, 256>>>(Wp2, Ws2, 1);
    k_copy_x<<<(N_NODESC * (DIM / 4) + 255) / 256, 256>>>(x);

    dim3 ggrid(DIM / 128, (N_NODESC + 127) / 128);   // (4, 391)
    int aggrid = (N_NODESC + 3) / 4;                 // 12500

    // layer 1
    k_agg<<<aggrid, 256>>>(xh, agh);
    k_gemmh<<<ggrid, 256, GEMM_SMEM>>>(xh, agh, W0, b1, h1h);

    // layer 2
    k_agg<<<aggrid, 256>>>(h1h, agh);
    k_gemmh<<<ggrid, 256, GEMM_SMEM>>>(h1h, agh, W1, b2, h2h);

    // pool + classify
    k_pool<<<dim3((N_NODESC + 127) / 128, 4), 128>>>(h2h, batch);
    k_cnt<<<196, 256>>>(batch);
    k_cls<<<NUM_GRAPHS, 128>>>(Wc, bc, out);
}

// round 12
// speedup vs baseline: 2.2935x; 1.0020x over previous
#include <cuda_runtime.h>
#include <cuda_fp16.h>
#include <cstdint>
#include <math.h>

#define N_NODESC   50000
#define N_EDGESC   800000
#define DIM        512
#define KTOT       1024
#define NUM_GRAPHS 64
#define NUM_CLASSES 10
#define SCAN_NB    ((N_NODESC + 1 + 1023) / 1024)   // 49

typedef unsigned short u16;
typedef unsigned int   u32;

// ---------------- scratch (device globals; no allocation allowed) ----------
__device__ __align__(16) u16   g_xh [(size_t)N_NODESC * DIM];   // x, fp16
__device__ __align__(16) u16   g_agh[(size_t)N_NODESC * DIM];   // agg, fp16
__device__ __align__(16) u16   g_h1h[(size_t)N_NODESC * DIM];   // h1, fp16
__device__ __align__(16) u16   g_h2h[(size_t)N_NODESC * DIM];   // h2, fp16
__device__ __align__(16) u16   g_Wh [2][(size_t)DIM * KTOT];    // [layer][n][k], fp16
__device__ int   g_rowptr[N_NODESC + 1];
__device__ int   g_fill  [N_NODESC];
__device__ int   g_csr   [N_EDGESC];
__device__ int   g_hcol [2][4 * DIM];
__device__ float g_hsign[2][4 * DIM];
__device__ float g_gsum[NUM_GRAPHS * DIM];
__device__ float g_gcnt[NUM_GRAPHS];
__device__ int   g_bsum[64];
__device__ unsigned g_nz_ei = 0;      // static zero init; detect only ORs (idempotent)
__device__ unsigned g_nz_batch = 0;

// ---------------- helpers ---------------------------------------------------
__device__ __forceinline__ float eluf(float x) { return x > 0.f ? x : expm1f(x); }

__device__ __forceinline__ int idx_at(const int* p, long long i, bool is64) {
    return is64 ? p[2 * i] : p[i];
}

__device__ __forceinline__ void mma_f16(float* d, const u32* a, const u32* b) {
    asm volatile(
        "mma.sync.aligned.m16n8k16.row.col.f32.f16.f16.f32 "
        "{%0,%1,%2,%3},{%4,%5,%6,%7},{%8,%9},{%0,%1,%2,%3};\n"
        : "+f"(d[0]), "+f"(d[1]), "+f"(d[2]), "+f"(d[3])
        : "r"(a[0]), "r"(a[1]), "r"(a[2]), "r"(a[3]), "r"(b[0]), "r"(b[1]));
}
__device__ __forceinline__ void ldm_x4(u32& r0, u32& r1, u32& r2, u32& r3, u32 addr) {
    asm volatile("ldmatrix.sync.aligned.m8n8.x4.shared.b16 {%0,%1,%2,%3}, [%4];"
                 : "=r"(r0), "=r"(r1), "=r"(r2), "=r"(r3) : "r"(addr));
}
__device__ __forceinline__ void cp16(u32 dst, const void* src) {
    asm volatile("cp.async.cg.shared.global [%0], [%1], 16;\n" :: "r"(dst), "l"(src));
}
__device__ __forceinline__ void cp16z(u32 dst, const void* src, int nbytes) {
    asm volatile("cp.async.cg.shared.global [%0], [%1], 16, %2;\n"
                 :: "r"(dst), "l"(src), "r"(nbytes));
}
__device__ __forceinline__ u32 smem_u32(const void* p) {
    u32 a;
    asm("{ .reg .u64 t; cvta.to.shared.u64 t, %1; cvt.u32.u64 %0, t; }" : "=r"(a) : "l"(p));
    return a;
}
__device__ __forceinline__ u32 pack2h(float a, float b) {
    __half2 h = __floats2half2_rn(a, b);
    return *reinterpret_cast<u32*>(&h);
}
__device__ __forceinline__ void acc8(float* a, uint4 v) {
    float2 f0 = __half22float2(*reinterpret_cast<__half2*>(&v.x));
    float2 f1 = __half22float2(*reinterpret_cast<__half2*>(&v.y));
    float2 f2 = __half22float2(*reinterpret_cast<__half2*>(&v.z));
    float2 f3 = __half22float2(*reinterpret_cast<__half2*>(&v.w));
    a[0] += f0.x; a[1] += f0.y; a[2] += f1.x; a[3] += f1.y;
    a[4] += f2.x; a[5] += f2.y; a[6] += f3.x; a[7] += f3.y;
}

// ---------------- dtype detection ------------------------------------------
__global__ void k_detect(const unsigned* __restrict__ p, long long n, int which) {
    unsigned acc = 0;
    for (long long i = blockIdx.x * blockDim.x + threadIdx.x; i < n;
         i += (long long)gridDim.x * blockDim.x)
        acc |= p[2 * i + 1];
    acc |= __shfl_xor_sync(0xffffffffu, acc, 16);
    acc |= __shfl_xor_sync(0xffffffffu, acc, 8);
    acc |= __shfl_xor_sync(0xffffffffu, acc, 4);
    acc |= __shfl_xor_sync(0xffffffffu, acc, 2);
    acc |= __shfl_xor_sync(0xffffffffu, acc, 1);
    if ((threadIdx.x & 31) == 0 && acc) {
        if (which == 0) atomicOr(&g_nz_ei, acc);
        else            atomicOr(&g_nz_batch, acc);
    }
}

// ---------------- setup kernels --------------------------------------------
__global__ void k_zero_meta() {
    int i = blockIdx.x * blockDim.x + threadIdx.x;
    if (i <= N_NODESC) g_rowptr[i] = 0;
    if (i < NUM_GRAPHS * DIM) g_gsum[i] = 0.f;
    if (i < NUM_GRAPHS) g_gcnt[i] = 0.f;
}

__global__ void k_count(const int* __restrict__ ei) {
    bool is64 = (g_nz_ei == 0u);
    int e = blockIdx.x * blockDim.x + threadIdx.x;
    if (e < N_EDGESC) {
        int s = idx_at(ei, e, is64);
        atomicAdd(&g_rowptr[s + 1], 1);
    }
}

__global__ void k_scan1() {
    __shared__ int wsum[8];
    int b = blockIdx.x, t = threadIdx.x;
    int base = b * 1024 + t * 4;
    int v0, v1, v2, v3;
    v0 = (base + 0 <= N_NODESC) ? g_rowptr[base + 0] : 0;
    v1 = (base + 1 <= N_NODESC) ? g_rowptr[base + 1] : 0;
    v2 = (base + 2 <= N_NODESC) ? g_rowptr[base + 2] : 0;
    v3 = (base + 3 <= N_NODESC) ? g_rowptr[base + 3] : 0;
    v1 += v0; v2 += v1; v3 += v2;
    int lane = t & 31, w = t >> 5;
    int s = v3;
    #pragma unroll
    for (int o = 1; o < 32; o <<= 1) {
        int n = __shfl_up_sync(0xffffffffu, s, o);
        if (lane >= o) s += n;
    }
    if (lane == 31) wsum[w] = s;
    __syncthreads();
    if (t < 8) {
        int x = wsum[t];
        #pragma unroll
        for (int o = 1; o < 8; o <<= 1) {
            int n = __shfl_up_sync(0x000000ffu, x, o);
            if (t >= o) x += n;
        }
        wsum[t] = x;
    }
    __syncthreads();
    int excl = (w ? wsum[w - 1] : 0) + (s - v3);
    v0 += excl; v1 += excl; v2 += excl; v3 += excl;
    if (base + 0 <= N_NODESC) g_rowptr[base + 0] = v0;
    if (base + 1 <= N_NODESC) g_rowptr[base + 1] = v1;
    if (base + 2 <= N_NODESC) g_rowptr[base + 2] = v2;
    if (base + 3 <= N_NODESC) g_rowptr[base + 3] = v3;
    if (t == 0) g_bsum[b] = wsum[7];
}

__global__ void k_scan2() {
    __shared__ int sh[64];
    int t = threadIdx.x;
    sh[t] = (t < SCAN_NB) ? g_bsum[t] : 0;
    __syncthreads();
    for (int o = 1; o < 64; o <<= 1) {
        int a = (t >= o) ? sh[t - o] : 0;
        __syncthreads();
        sh[t] += a;
        __syncthreads();
    }
    g_bsum[t] = sh[t];
}

__global__ void k_scan3() {
    int b = blockIdx.x, t = threadIdx.x;
    int add = b ? g_bsum[b - 1] : 0;
    int base = b * 1024 + t * 4;
    #pragma unroll
    for (int i = 0; i < 4; ++i) {
        int idx = base + i;
        if (idx <= N_NODESC) {
            int r = g_rowptr[idx] + add;
            g_rowptr[idx] = r;
            if (idx < N_NODESC) g_fill[idx] = r;
        }
    }
}

__global__ void k_scatter(const int* __restrict__ ei) {
    bool is64 = (g_nz_ei == 0u);
    int e = blockIdx.x * blockDim.x + threadIdx.x;
    if (e < N_EDGESC) {
        int s = idx_at(ei, e, is64);
        int d = idx_at(ei, (long long)N_EDGESC + e, is64);
        int pos = atomicAdd(&g_fill[s], 1);
        g_csr[pos] = d;
    }
}

// one warp per hash row: coalesced scan + ballot pick
__global__ void k_hash(const float* __restrict__ Hm, int l) {
    int warp = (blockIdx.x * blockDim.x + threadIdx.x) >> 5;
    int lane = threadIdx.x & 31;
    if (warp >= 4 * DIM) return;
    const float* row = Hm + (size_t)warp * 128;
    int col = 0; float sgn = 0.f;
    #pragma unroll
    for (int i = 0; i < 4; ++i) {
        float v = row[lane + i * 32];
        if (v != 0.f) { col = lane + i * 32; sgn = v; }
    }
    unsigned m = __ballot_sync(0xffffffffu, sgn != 0.f);
    if (m) {
        int src = __ffs(m) - 1;
        col = __shfl_sync(0xffffffffu, col, src);
        sgn = __shfl_sync(0xffffffffu, sgn, src);
    }
    if (lane == 0) { g_hcol[l][warp] = col; g_hsign[l][warp] = sgn; }
}

// g_Wh[l][n=j][k=r] = fp16( cat(Ws, Wp_eff)[r][j] )
__global__ void k_buildW(const float* __restrict__ Wp, const float* __restrict__ Ws, int l) {
    int idx = blockIdx.x * blockDim.x + threadIdx.x;
    if (idx >= KTOT * DIM) return;
    int r = idx >> 9;        // k
    int j = idx & 511;       // n
    float w;
    if (r < 512) {
        w = Ws[r * DIM + j];
    } else {
        int d = r - 512;
        w = 0.f;
        #pragma unroll
        for (int k = 0; k < 4; ++k) {
            int c = g_hcol[l][k * DIM + d];
            w += g_hsign[l][k * DIM + d] * Wp[(size_t)(k * 128 + c) * DIM + j];
        }
    }
    __half h = __float2half_rn(w);
    g_Wh[l][(size_t)j * KTOT + r] = *reinterpret_cast<u16*>(&h);
}

// x -> fp16 plane
__global__ void k_copy_x(const float* __restrict__ x) {
    int i = blockIdx.x * blockDim.x + threadIdx.x;   // float4 index
    if (i >= N_NODESC * (DIM / 4)) return;
    size_t off = (size_t)i * 4;
    float4 v = *(const float4*)(x + off);
    uint2 p;
    p.x = pack2h(v.x, v.y);
    p.y = pack2h(v.z, v.w);
    *(uint2*)(g_xh + off) = p;
}

// ---------------- aggregation: gather-mean over fp16 plane -------------------
__global__ void __launch_bounds__(256)
k_agg(const u16* __restrict__ h, u16* __restrict__ agg) {
    int n = blockIdx.x * 4 + (threadIdx.x >> 6);
    if (n >= N_NODESC) return;
    int t = threadIdx.x & 63;
    int s = g_rowptr[n], e = g_rowptr[n + 1];
    size_t off = (size_t)n * DIM + t * 8;
    uint4 o;
    if (e == s) {
        o = *(const uint4*)(h + off);
    } else {
        float a[8] = {0.f, 0.f, 0.f, 0.f, 0.f, 0.f, 0.f, 0.f};
        int j = s;
        for (; j + 2 <= e; j += 2) {
            int d0 = g_csr[j], d1 = g_csr[j + 1];
            uint4 v0 = *(const uint4*)(h + (size_t)d0 * DIM + t * 8);
            uint4 v1 = *(const uint4*)(h + (size_t)d1 * DIM + t * 8);
            acc8(a, v0);
            acc8(a, v1);
        }
        if (j < e) {
            uint4 v = *(const uint4*)(h + (size_t)g_csr[j] * DIM + t * 8);
            acc8(a, v);
        }
        float inv = 1.f / (float)(e - s);
        o.x = pack2h(a[0] * inv, a[1] * inv);
        o.y = pack2h(a[2] * inv, a[3] * inv);
        o.z = pack2h(a[4] * inv, a[5] * inv);
        o.w = pack2h(a[6] * inv, a[7] * inv);
    }
    *(uint4*)(agg + off) = o;
}

// ---------------- fp16 GEMM: out = elu([h|agg] @ W + b) ----------------------
// BM=128, BN=128, BK=32 halves, 4-stage cp.async ring, one sync per slab.
#define AWB      80                      // bytes per smem row
#define PLANEB   (128 * AWB)             // 10240 bytes
#define STAGEB   (2 * PLANEB)            // 20480 bytes
#define NSTAGE   4
#define GEMM_SMEM (NSTAGE * STAGEB)      // 81920 bytes

__global__ void __launch_bounds__(256, 2)
k_gemmh(const u16* __restrict__ Hh, const u16* __restrict__ Gh,
        const u16* __restrict__ W, const float* __restrict__ bias,
        u16* __restrict__ C16)
{
    extern __shared__ char S[];
    const u32 sb   = smem_u32(S);
    const int tid  = threadIdx.x;
    const int lane = tid & 31;
    const int wid  = tid >> 5;
    const int g    = lane >> 2;
    const int t4   = lane & 3;
    const int wm   = (wid & 1) * 64;
    const int wn   = (wid >> 1) * 32;
    const int m0   = blockIdx.y * 128;
    const int n0   = blockIdx.x * 128;

    float acc[4][4][4];
    #pragma unroll
    for (int i = 0; i < 4; ++i)
        #pragma unroll
        for (int j = 0; j < 4; ++j)
            #pragma unroll
            for (int k = 0; k < 4; ++k) acc[i][j][k] = 0.f;

    const int qr = tid >> 2;     // 0..63
    const int qc = tid & 3;      // 16B chunk within row

    auto load_stage = [&](int kt) {
        const int st = kt & (NSTAGE - 1);
        const int kk = kt * 32;
        const u16* Asrc = (kk & 512) ? Gh : Hh;
        const int kc = kk & 511;
        const u32 ab = sb + st * STAGEB;
        #pragma unroll
        for (int i = 0; i < 2; ++i) {
            int row = qr + i * 64;
            int grow = m0 + row;
            int ok = (grow < N_NODESC) ? 16 : 0;
            const u16* src = Asrc + (size_t)(grow < N_NODESC ? grow : 0) * DIM + kc + qc * 8;
            cp16z(ab + row * AWB + qc * 16, src, ok);
        }
        const u32 bb = sb + st * STAGEB + PLANEB;
        #pragma unroll
        for (int i = 0; i < 2; ++i) {
            int row = qr + i * 64;
            const u16* src = W + (size_t)(n0 + row) * KTOT + kk + qc * 8;
            cp16(bb + row * AWB + qc * 16, src);
        }
        asm volatile("cp.async.commit_group;\n");
    };

    load_stage(0);
    load_stage(1);
    load_stage(2);

    const u32 a_row  = wm + (lane & 15);
    const u32 a_koff = (lane >> 4) << 4;
    const u32 b_row  = wn + ((lane >> 4) << 3) + (lane & 7);
    const u32 b_koff = ((lane >> 3) & 1) << 4;

    const int KT = KTOT / 32;   // 32
    for (int kt = 0; kt < KT; ++kt) {
        const int st = kt & (NSTAGE - 1);
        asm volatile("cp.async.wait_group 2;\n");
        __syncthreads();
        // issue next load BEFORE compute (distinct ring slot; prev reader synced)
        if (kt + 3 < KT) load_stage(kt + 3);
        else asm volatile("cp.async.commit_group;\n");   // keep group count valid
        const u32 ab = sb + st * STAGEB;
        const u32 bb = ab + PLANEB;
        #pragma unroll
        for (int ks2 = 0; ks2 < 2; ++ks2) {
            const u32 ko = ks2 << 5;
            u32 a[4][4], b[4][2];
            #pragma unroll
            for (int mi = 0; mi < 4; ++mi)
                ldm_x4(a[mi][0], a[mi][1], a[mi][2], a[mi][3],
                       ab + (a_row + mi * 16) * AWB + a_koff + ko);
            #pragma unroll
            for (int nip = 0; nip < 2; ++nip)
                ldm_x4(b[nip * 2][0], b[nip * 2][1], b[nip * 2 + 1][0], b[nip * 2 + 1][1],
                       bb + (b_row + nip * 16) * AWB + b_koff + ko);
            #pragma unroll
            for (int mi = 0; mi < 4; ++mi)
                #pragma unroll
                for (int ni = 0; ni < 4; ++ni)
                    mma_f16(acc[mi][ni], a[mi], b[ni]);
        }
    }

    // epilogue: bias + elu -> fp16 plane
    #pragma unroll
    for (int mi = 0; mi < 4; ++mi) {
        int rr0 = m0 + wm + mi * 16 + g;
        #pragma unroll
        for (int ni = 0; ni < 4; ++ni) {
            int col = n0 + wn + ni * 8 + 2 * t4;
            float bb0 = bias[col], bb1 = bias[col + 1];
            #pragma unroll
            for (int half = 0; half < 2; ++half) {
                int row = rr0 + half * 8;
                if (row < N_NODESC) {
                    float vx = eluf(acc[mi][ni][half * 2 + 0] + bb0);
                    float vy = eluf(acc[mi][ni][half * 2 + 1] + bb1);
                    *(u32*)(C16 + (size_t)row * DIM + col) = pack2h(vx, vy);
                }
            }
        }
    }
}

// ---------------- pooling + classifier --------------------------------------
__global__ void k_pool(const u16* __restrict__ h, const int* __restrict__ batch) {
    bool is64 = (g_nz_batch == 0u);
    int d  = blockIdx.y * 128 + threadIdx.x;
    int n0 = blockIdx.x * 128;
    int ne = min(n0 + 128, N_NODESC);
    int cur = idx_at(batch, n0, is64);
    float acc = 0.f;
    for (int n = n0; n < ne; ++n) {
        int b = idx_at(batch, n, is64);
        if (b != cur) { atomicAdd(&g_gsum[cur * DIM + d], acc); acc = 0.f; cur = b; }
        acc += __half2float(*reinterpret_cast<const __half*>(h + (size_t)n * DIM + d));
    }
    atomicAdd(&g_gsum[cur * DIM + d], acc);
}

__global__ void k_cnt(const int* __restrict__ batch) {
    __shared__ int hist[NUM_GRAPHS];
    int t = threadIdx.x;
    if (t < NUM_GRAPHS) hist[t] = 0;
    __syncthreads();
    bool is64 = (g_nz_batch == 0u);
    int n = blockIdx.x * blockDim.x + t;
    if (n < N_NODESC) atomicAdd(&hist[idx_at(batch, n, is64)], 1);
    __syncthreads();
    if (t < NUM_GRAPHS && hist[t]) atomicAdd(&g_gcnt[t], (float)hist[t]);
}

__global__ void k_cls(const float* __restrict__ Wc, const float* __restrict__ bc,
                      float* __restrict__ out) {
    int gid = blockIdx.x;
    int t = threadIdx.x;
    __shared__ float gv[DIM];
    __shared__ float red[NUM_CLASSES][128];
    float inv = 1.f / fmaxf(g_gcnt[gid], 1.f);
    for (int d = t; d < DIM; d += 128) gv[d] = g_gsum[gid * DIM + d] * inv;
    __syncthreads();
    float p[NUM_CLASSES];
    #pragma unroll
    for (int c = 0; c < NUM_CLASSES; ++c) p[c] = 0.f;
    for (int d = t; d < DIM; d += 128) {
        float v = gv[d];
        #pragma unroll
        for (int c = 0; c < NUM_CLASSES; ++c) p[c] += v * Wc[d * NUM_CLASSES + c];
    }
    #pragma unroll
    for (int c = 0; c < NUM_CLASSES; ++c) red[c][t] = p[c];
    __syncthreads();
    for (int off = 64; off > 0; off >>= 1) {
        if (t < off)
            #pragma unroll
            for (int c = 0; c < NUM_CLASSES; ++c) red[c][t] += red[c][t + off];
        __syncthreads();
    }
    if (t < NUM_CLASSES) out[gid * NUM_CLASSES + t] = red[t][0] + bc[t];
}

// ---------------- launch -----------------------------------------------------
extern "C" void kernel_launch(void* const* d_in, const int* in_sizes, int n_in,
                              void* d_out, int out_size) {
    const float* x     = (const float*)d_in[0];
    const int*   ei    = (const int*)d_in[1];
    const int*   batch = (const int*)d_in[2];
    const float* Hm1   = (const float*)d_in[3];
    const float* Wp1   = (const float*)d_in[4];
    const float* Ws1   = (const float*)d_in[5];
    const float* b1    = (const float*)d_in[6];
    const float* Hm2   = (const float*)d_in[7];
    const float* Wp2   = (const float*)d_in[8];
    const float* Ws2   = (const float*)d_in[9];
    const float* b2    = (const float*)d_in[10];
    const float* Wc    = (const float*)d_in[11];
    const float* bc    = (const float*)d_in[12];
    float*       out   = (float*)d_out;

    u16 *xh, *agh, *h1h, *h2h, *wh;
    cudaGetSymbolAddress((void**)&xh,  g_xh);
    cudaGetSymbolAddress((void**)&agh, g_agh);
    cudaGetSymbolAddress((void**)&h1h, g_h1h);
    cudaGetSymbolAddress((void**)&h2h, g_h2h);
    cudaGetSymbolAddress((void**)&wh,  g_Wh);
    u16* W0 = wh;
    u16* W1 = wh + (size_t)DIM * KTOT;

    cudaFuncSetAttribute(k_gemmh, cudaFuncAttributeMaxDynamicSharedMemorySize, GEMM_SMEM);

    // dtype detection (flags statically zero-initialized; OR is idempotent across replays)
    k_detect<<<256, 256>>>((const unsigned*)ei, N_EDGESC, 0);
    k_detect<<<64, 256>>>((const unsigned*)batch, N_NODESC / 2, 1);

    // setup
    k_zero_meta<<<196, 256>>>();
    k_count<<<(N_EDGESC + 255) / 256, 256>>>(ei);
    k_scan1<<<SCAN_NB, 256>>>();
    k_scan2<<<1, 64>>>();
    k_scan3<<<SCAN_NB, 256>>>();
    k_scatter<<<(N_EDGESC + 255) / 256, 256>>>(ei);
    k_hash<<<(4 * DIM * 32 + 255) / 256, 256>>>(Hm1, 0);
    k_hash<<<(4 * DIM * 32 + 255) / 256, 256>>>(Hm2, 1);
    k_buildW<<<(KTOT * DIM + 255) / 256, 256>>>(Wp1, Ws1, 0);
    k_buildW<<<(KTOT * DIM + 255) / 256, 256>>>(Wp2, Ws2, 1);
    k_copy_x<<<(N_NODESC * (DIM / 4) + 255) / 256, 256>>>(x);

    dim3 ggrid(DIM / 128, (N_NODESC + 127) / 128);   // (4, 391)
    int aggrid = (N_NODESC + 3) / 4;                 // 12500

    // layer 1
    k_agg<<<aggrid, 256>>>(xh, agh);
    k_gemmh<<<ggrid, 256, GEMM_SMEM>>>(xh, agh, W0, b1, h1h);

    // layer 2
    k_agg<<<aggrid, 256>>>(h1h, agh);
    k_gemmh<<<ggrid, 256, GEMM_SMEM>>>(h1h, agh, W1, b2, h2h);

    // pool + classify
    k_pool<<<dim3((N_NODESC + 127) / 128, 4), 128>>>(h2h, batch);
    k_cnt<<<196, 256>>>(batch);
    k_cls<<<NUM_GRAPHS, 128>>>(Wc, bc, out);
}